// round 11
// baseline (speedup 1.0000x reference)
#include <cuda_runtime.h>
#include <cuda_bf16.h>
#include <math.h>

#define NN 50000
#define MP 50048          // NN padded to 128
#define EE 800000
#define PP 400000
#define NB_SCAN 196       // ceil(NN/256)

typedef unsigned short ushort_t;
typedef unsigned int uint_t;

// ---------------- scratch (device globals) ----------------------------------
static __device__ __align__(16) ushort_t g_xh[MP * 128];
static __device__ __align__(16) ushort_t g_xl[MP * 128];
static __device__ __align__(16) ushort_t g_txh[MP * 128];
static __device__ __align__(16) ushort_t g_txl[MP * 128];
static __device__ __align__(16) ushort_t g_hh[MP * 320];
static __device__ __align__(16) ushort_t g_hl[MP * 320];
static __device__ __align__(16) ushort_t g_w1h[2 * 128 * 384];  // [K=128, N=384 padded]
static __device__ __align__(16) ushort_t g_w1l[2 * 128 * 384];
static __device__ __align__(16) ushort_t g_w2h[320 * 256];      // cat: [W2[1] | W2[0]]
static __device__ __align__(16) ushort_t g_w2l[320 * 256];
static __device__ __align__(16) ushort_t g_l1h[128 * 128];
static __device__ __align__(16) ushort_t g_l1l[128 * 128];
static __device__ __align__(16) ushort_t g_l2h[128 * 128];
static __device__ __align__(16) ushort_t g_l2l[128 * 128];

static __device__ __align__(16) float g_h1f[NN * 300];       // x@W1[0]+b1 (fp32)
static __device__ __align__(16) float g_y2x[MP * 256];       // [y2 | x1raw]
static __device__ __align__(16) float g_t2[NN * 100];
static __device__ __align__(16) float g_x2[NN * 100];
static __device__ __align__(16) float g_z[NN * 100];
static __device__ __align__(16) float g_y3[NN * 2];
static __device__ __align__(16) float g_t3[NN * 2];
static __device__ float g_dinv[NN];
static __device__ int   g_deg[NN];
static __device__ int   g_cnt[NN];
static __device__ int   g_fill[NN];
static __device__ int   g_rowptr[NN + 1];
static __device__ int   g_bsum[NB_SCAN];
static __device__ int   g_boff[NB_SCAN];
static __device__ int   g_csr_src[EE];
static __device__ float g_csr_w[EE];
static __device__ float g_loss;

// ---------------- helpers ----------------------------------------------------
__device__ __forceinline__ void split1(float v, ushort_t& h, ushort_t& l) {
    __nv_bfloat16 bh = __float2bfloat16_rn(v);
    h = __bfloat16_as_ushort(bh);
    float r = v - __bfloat162float(bh);
    l = __bfloat16_as_ushort(__float2bfloat16_rn(r));
}

__device__ __forceinline__ void ldsm4(uint_t* r, uint_t addr) {
    asm volatile("ldmatrix.sync.aligned.m8n8.x4.shared.b16 {%0,%1,%2,%3}, [%4];"
                 : "=r"(r[0]), "=r"(r[1]), "=r"(r[2]), "=r"(r[3]) : "r"(addr));
}
__device__ __forceinline__ void ldsm4t(uint_t* r, uint_t addr) {
    asm volatile("ldmatrix.sync.aligned.m8n8.x4.trans.shared.b16 {%0,%1,%2,%3}, [%4];"
                 : "=r"(r[0]), "=r"(r[1]), "=r"(r[2]), "=r"(r[3]) : "r"(addr));
}
__device__ __forceinline__ void mma_bf16(float* d, const uint_t* a, uint_t b0, uint_t b1) {
    asm volatile(
        "mma.sync.aligned.m16n8k16.row.col.f32.bf16.bf16.f32 "
        "{%0,%1,%2,%3},{%4,%5,%6,%7},{%8,%9},{%0,%1,%2,%3};"
        : "+f"(d[0]), "+f"(d[1]), "+f"(d[2]), "+f"(d[3])
        : "r"(a[0]), "r"(a[1]), "r"(a[2]), "r"(a[3]), "r"(b0), "r"(b1));
}
__device__ __forceinline__ void cp16(uint_t dst, const void* src) {
    asm volatile("cp.async.cg.shared.global [%0], [%1], 16;\n" :: "r"(dst), "l"(src));
}

// ---------------- graph preprocessing ----------------------------------------
__global__ void k_zero() {
    int i = blockIdx.x * blockDim.x + threadIdx.x;
    if (i < NN) { g_deg[i] = 0; g_cnt[i] = 0; g_fill[i] = 0; }
    if (i == 0) g_loss = 0.0f;
}

__global__ void k_degcnt(const int* __restrict__ ei) {
    int e = blockIdx.x * blockDim.x + threadIdx.x;
    if (e < EE) {
        atomicAdd(&g_deg[ei[e]], 1);
        atomicAdd(&g_cnt[ei[EE + e]], 1);
    }
}

__global__ void k_dinv() {
    int i = blockIdx.x * blockDim.x + threadIdx.x;
    if (i < NN) {
        int d = g_deg[i];
        g_dinv[i] = (d > 0) ? rsqrtf((float)d) : 0.0f;
    }
}

__global__ void k_scan1() {
    __shared__ int s[256];
    int t = threadIdx.x;
    int i = blockIdx.x * 256 + t;
    s[t] = (i < NN) ? g_cnt[i] : 0;
    __syncthreads();
    for (int o = 128; o > 0; o >>= 1) {
        if (t < o) s[t] += s[t + o];
        __syncthreads();
    }
    if (t == 0) g_bsum[blockIdx.x] = s[0];
}

__global__ void k_scan2() {
    __shared__ int s[256];
    int t = threadIdx.x;
    int v = (t < NB_SCAN) ? g_bsum[t] : 0;
    s[t] = v;
    __syncthreads();
    for (int o = 1; o < 256; o <<= 1) {
        int tv = (t >= o) ? s[t - o] : 0;
        __syncthreads();
        s[t] += tv;
        __syncthreads();
    }
    if (t < NB_SCAN) g_boff[t] = s[t] - v;
    if (t == 255) g_rowptr[NN] = s[255];
}

__global__ void k_scan3() {
    __shared__ int s[256];
    int t = threadIdx.x;
    int i = blockIdx.x * 256 + t;
    int v = (i < NN) ? g_cnt[i] : 0;
    s[t] = v;
    __syncthreads();
    for (int o = 1; o < 256; o <<= 1) {
        int tv = (t >= o) ? s[t - o] : 0;
        __syncthreads();
        s[t] += tv;
        __syncthreads();
    }
    if (i < NN) g_rowptr[i] = g_boff[blockIdx.x] + s[t] - v;
}

__global__ void k_fill(const int* __restrict__ ei) {
    int e = blockIdx.x * blockDim.x + threadIdx.x;
    if (e < EE) {
        int s = ei[e];
        int d = ei[EE + e];
        int pos = g_rowptr[d] + atomicAdd(&g_fill[d], 1);
        g_csr_src[pos] = s;
        g_csr_w[pos] = -g_dinv[s] * g_dinv[d];
    }
}

// ---------------- conversions --------------------------------------------------
__global__ void k_conv_x(const float* __restrict__ x) {
    int idx = blockIdx.x * blockDim.x + threadIdx.x;
    if (idx >= MP * 32) return;
    int row = idx >> 5;
    float4 v = (row < NN) ? ((const float4*)x)[idx] : make_float4(0.f, 0.f, 0.f, 0.f);
    ushort_t h0, h1, h2, h3, l0, l1, l2, l3;
    split1(v.x, h0, l0); split1(v.y, h1, l1);
    split1(v.z, h2, l2); split1(v.w, h3, l3);
    ((uint2*)g_xh)[idx] = make_uint2((uint_t)h0 | ((uint_t)h1 << 16), (uint_t)h2 | ((uint_t)h3 << 16));
    ((uint2*)g_xl)[idx] = make_uint2((uint_t)l0 | ((uint_t)l1 << 16), (uint_t)l2 | ((uint_t)l3 << 16));
}

__global__ void k_conv_w(const float* __restrict__ src, ushort_t* __restrict__ dh,
                         ushort_t* __restrict__ dl, int K, int N, int Kp, int Np, int trans) {
    int idx = blockIdx.x * blockDim.x + threadIdx.x;
    if (idx >= Kp * Np) return;
    int k = idx / Np, n = idx % Np;
    float v = 0.f;
    if (k < K && n < N) v = trans ? src[n * K + k] : src[k * N + n];
    ushort_t h, l;
    split1(v, h, l);
    dh[idx] = h;
    dl[idx] = l;
}

// W2 concatenated conversion: src [300,100] -> dst[320,256] cols [coff, coff+128)
__global__ void k_conv_wc(const float* __restrict__ src, ushort_t* __restrict__ dh,
                          ushort_t* __restrict__ dl, int coff) {
    int idx = blockIdx.x * blockDim.x + threadIdx.x;
    if (idx >= 320 * 128) return;
    int k = idx >> 7, n = idx & 127;
    float v = (k < 300 && n < 100) ? src[k * 100 + n] : 0.f;
    ushort_t h, l;
    split1(v, h, l);
    dh[k * 256 + coff + n] = h;
    dl[k * 256 + coff + n] = l;
}

__global__ void k_zero_hpad() {
    int idx = blockIdx.x * blockDim.x + threadIdx.x;
    if (idx < (MP - NN) * 320) {
        g_hh[(size_t)NN * 320 + idx] = 0;
        g_hl[(size_t)NN * 320 + idx] = 0;
    }
}

// ---------------- gathers -------------------------------------------------------
__global__ void k_gather128bf(const float* __restrict__ x) {
    int gw = (blockIdx.x * blockDim.x + threadIdx.x) >> 5;
    int lane = threadIdx.x & 31;
    if (gw >= MP) return;
    float4 acc = make_float4(0.f, 0.f, 0.f, 0.f);
    if (gw < NN) {
        int beg = g_rowptr[gw], end = g_rowptr[gw + 1];
        const float4* sf = (const float4*)x;
        for (int e = beg; e < end; e++) {
            int s = g_csr_src[e];
            float w = g_csr_w[e];
            float4 v = sf[(size_t)s * 32 + lane];
            acc.x += w * v.x; acc.y += w * v.y;
            acc.z += w * v.z; acc.w += w * v.w;
        }
    }
    ushort_t h0, h1, h2, h3, l0, l1, l2, l3;
    split1(acc.x, h0, l0); split1(acc.y, h1, l1);
    split1(acc.z, h2, l2); split1(acc.w, h3, l3);
    size_t idx = (size_t)gw * 32 + lane;
    ((uint2*)g_txh)[idx] = make_uint2((uint_t)h0 | ((uint_t)h1 << 16), (uint_t)h2 | ((uint_t)h3 << 16));
    ((uint2*)g_txl)[idx] = make_uint2((uint_t)l0 | ((uint_t)l1 << 16), (uint_t)l2 | ((uint_t)l3 << 16));
}

template <int F4, int LD4>
__global__ void k_gather(const float* __restrict__ SF, float* __restrict__ DF) {
    int gw = (blockIdx.x * blockDim.x + threadIdx.x) >> 5;
    int lane = threadIdx.x & 31;
    if (gw >= NN) return;
    int beg = g_rowptr[gw], end = g_rowptr[gw + 1];
    if (lane < F4) {
        const float4* sf = (const float4*)SF;
        float4 acc = make_float4(0.f, 0.f, 0.f, 0.f);
        for (int e = beg; e < end; e++) {
            int s = g_csr_src[e];
            float w = g_csr_w[e];
            float4 v = sf[(size_t)s * LD4 + lane];
            acc.x += w * v.x; acc.y += w * v.y;
            acc.z += w * v.z; acc.w += w * v.w;
        }
        ((float4*)DF)[(size_t)gw * F4 + lane] = acc;
    }
}

__global__ void k_gather2(const float* __restrict__ SF, float* __restrict__ DF) {
    int n = blockIdx.x * blockDim.x + threadIdx.x;
    if (n >= NN) return;
    int beg = g_rowptr[n], end = g_rowptr[n + 1];
    float a0 = 0.f, a1 = 0.f;
    for (int e = beg; e < end; e++) {
        int s = g_csr_src[e];
        float w = g_csr_w[e];
        a0 += w * SF[2 * s];
        a1 += w * SF[2 * s + 1];
    }
    DF[2 * n] = a0;
    DF[2 * n + 1] = a1;
}

// ---------------- bf16x3 tensor-core GEMM, 2-stage cp.async, WN-templated -------
// CTA tile 128 x WN; 8 warps (4x2); warp tile 32 x (WN/2).
#define A_L_OFF 5120

template <int WN>
__device__ __forceinline__ void issue_tile(
    uint_t sbase, int tid,
    const ushort_t* __restrict__ Ah, const ushort_t* __restrict__ Al, int lda, int rowBase,
    const ushort_t* __restrict__ Bh, const ushort_t* __restrict__ Bl, int ldb, int colBase,
    int k0) {
    constexpr int BST = WN + 8;
    constexpr int B_H_OFFt = 10240;
    constexpr int B_L_OFFt = 10240 + 32 * BST;
    constexpr int BCH = WN / 8;          // 16B chunks per B row
#pragma unroll
    for (int i = 0; i < 4; i++) {
        int idx = tid + i * 256;
        int arr = idx >> 9, rem = idx & 511;
        int row = rem >> 2, ch = rem & 3;
        const ushort_t* src = (arr ? Al : Ah) + (size_t)(rowBase + row) * lda + k0 + ch * 8;
        uint_t dst = sbase + (uint_t)((arr ? A_L_OFF : 0) + row * 40 + ch * 8) * 2;
        cp16(dst, src);
    }
    constexpr int BTOT = 2 * 32 * BCH;   // total B chunks (hi+lo)
#pragma unroll
    for (int i = 0; i < BTOT / 256; i++) {
        int idx = tid + i * 256;
        int arr = (idx >= 32 * BCH) ? 1 : 0;
        int rem = idx - arr * 32 * BCH;
        int row = rem / BCH, ch = rem % BCH;
        const ushort_t* src = (arr ? Bl : Bh) + (size_t)(k0 + row) * ldb + colBase + ch * 8;
        uint_t dst = sbase + (uint_t)((arr ? B_L_OFFt : B_H_OFFt) + row * BST + ch * 8) * 2;
        cp16(dst, src);
    }
    asm volatile("cp.async.commit_group;\n");
}

template <int WN>
__global__ __launch_bounds__(256)
void k_bgemm(const ushort_t* __restrict__ Ah1, const ushort_t* __restrict__ Al1, int lda1,
             const ushort_t* __restrict__ Bh1, const ushort_t* __restrict__ Bl1,
             const ushort_t* __restrict__ Ah2, const ushort_t* __restrict__ Al2, int lda2,
             const ushort_t* __restrict__ Bh2, const ushort_t* __restrict__ Bl2,
             int K1, int K2, int ldb,
             int M, int N,
             const float* __restrict__ bias, const float* __restrict__ addend,
             const float* __restrict__ post1, const float* __restrict__ post2, int relu,
             float* __restrict__ Cf1, float* __restrict__ Cf2,
             ushort_t* __restrict__ Ch, ushort_t* __restrict__ Cl,
             int ldc) {
    constexpr int BST = WN + 8;
    constexpr int B_H_OFFt = 10240;
    constexpr int STAGE = 10240 + 64 * BST;
    constexpr int NP = WN / 32;          // 16-wide B fragments per warp
    constexpr int NREG = WN / 16;        // 8-wide accum groups per warp

    extern __shared__ __align__(16) ushort_t sm[];
    uint_t sbase0 = (uint_t)__cvta_generic_to_shared(sm);

    int tid = threadIdx.x, lane = tid & 31, wid = tid >> 5;
    int warp_m = wid & 3, warp_n = wid >> 2;
    int rowBase = blockIdx.y * 128, colBase = blockIdx.x * WN;

    float acc[2][NREG][4];
#pragma unroll
    for (int m = 0; m < 2; m++)
#pragma unroll
        for (int n = 0; n < NREG; n++)
#pragma unroll
            for (int q = 0; q < 4; q++) acc[m][n][q] = 0.f;

    int T1 = K1 / 32;
    int T2 = (Ah2 != nullptr) ? (K2 / 32) : 0;
    int T = T1 + T2;

#define ISSUE(t)                                                                          \
    do {                                                                                  \
        int _t = (t);                                                                     \
        uint_t _sb = sbase0 + (uint_t)((_t & 1) * STAGE) * 2;                             \
        if (_t < T1)                                                                      \
            issue_tile<WN>(_sb, tid, Ah1, Al1, lda1, rowBase, Bh1, Bl1, ldb, colBase, _t * 32); \
        else                                                                              \
            issue_tile<WN>(_sb, tid, Ah2, Al2, lda2, rowBase, Bh2, Bl2, ldb, colBase, (_t - T1) * 32); \
    } while (0)

    ISSUE(0);

    for (int t = 0; t < T; t++) {
        if (t + 1 < T) {
            ISSUE(t + 1);
            asm volatile("cp.async.wait_group 1;\n");
        } else {
            asm volatile("cp.async.wait_group 0;\n");
        }
        __syncthreads();

        uint_t sA = sbase0 + (uint_t)((t & 1) * STAGE) * 2;
        uint_t sB = sA + (uint_t)B_H_OFFt * 2;

#pragma unroll
        for (int kk = 0; kk < 32; kk += 16) {
            uint_t ah[2][4], al[2][4], bh[NP][4], bl[NP][4];
            int g = lane >> 3, r = lane & 7;
#pragma unroll
            for (int m = 0; m < 2; m++) {
                int arow = warp_m * 32 + m * 16 + r + (g & 1) * 8;
                int acol = kk + (g >> 1) * 8;
                uint_t off = (uint_t)(arow * 40 + acol) * 2;
                ldsm4(ah[m], sA + off);
                ldsm4(al[m], sA + (uint_t)A_L_OFF * 2 + off);
            }
#pragma unroll
            for (int np = 0; np < NP; np++) {
                int brow = kk + r + (g & 1) * 8;
                int bcol = warp_n * (WN / 2) + np * 16 + (g >> 1) * 8;
                uint_t off = (uint_t)(brow * BST + bcol) * 2;
                ldsm4t(bh[np], sB + off);
                ldsm4t(bl[np], sB + (uint_t)(32 * BST) * 2 + off);
            }
#pragma unroll
            for (int m = 0; m < 2; m++)
#pragma unroll
                for (int n = 0; n < NREG; n++) {
                    uint_t b0h = bh[n >> 1][(n & 1) * 2], b1h = bh[n >> 1][(n & 1) * 2 + 1];
                    uint_t b0l = bl[n >> 1][(n & 1) * 2], b1l = bl[n >> 1][(n & 1) * 2 + 1];
                    mma_bf16(acc[m][n], ah[m], b0h, b1h);  // hi*hi
                    mma_bf16(acc[m][n], ah[m], b0l, b1l);  // hi*lo
                    mma_bf16(acc[m][n], al[m], b0h, b1h);  // lo*hi
                }
        }
        __syncthreads();
    }
#undef ISSUE

    // epilogue
#pragma unroll
    for (int m = 0; m < 2; m++)
#pragma unroll
        for (int n = 0; n < NREG; n++) {
#pragma unroll
            for (int half = 0; half < 2; half++) {
                float v0 = acc[m][n][half * 2 + 0];
                float v1 = acc[m][n][half * 2 + 1];
                int gr = rowBase + warp_m * 32 + m * 16 + (lane >> 2) + half * 8;
                int gc = colBase + warp_n * (WN / 2) + n * 8 + (lane & 3) * 2;
                if (gr >= M || gc >= N) continue;
                if (bias) { v0 += bias[gc]; v1 += bias[gc + 1]; }
                if (addend) {
                    v0 += addend[(size_t)gr * N + gc];
                    v1 += addend[(size_t)gr * N + gc + 1];
                }
                if (relu) { v0 = fmaxf(v0, 0.f); v1 = fmaxf(v1, 0.f); }
                size_t oidx = (size_t)gr * ldc + gc;
                if (Cf1) {
                    float a0 = v0, a1 = v1;
                    if (post1) {
                        float2 p = *(const float2*)&post1[oidx];
                        a0 += p.x; a1 += p.y;
                    }
                    float2 o; o.x = a0; o.y = a1;
                    *(float2*)&Cf1[oidx] = o;
                }
                if (Cf2) {
                    float a0 = v0, a1 = v1;
                    if (post2) {
                        float2 p = *(const float2*)&post2[oidx];
                        a0 += p.x; a1 += p.y;
                    }
                    float2 o; o.x = a0; o.y = a1;
                    *(float2*)&Cf2[oidx] = o;
                }
                if (Ch) {
                    ushort_t h0, l0, h1, l1;
                    split1(v0, h0, l0);
                    split1(v1, h1, l1);
                    *(uint_t*)&Ch[oidx] = (uint_t)h0 | ((uint_t)h1 << 16);
                    *(uint_t*)&Cl[oidx] = (uint_t)l0 | ((uint_t)l1 << 16);
                }
            }
        }
}

#define SMEM64  ((10240 + 64 * 72) * 4)
#define SMEM128 ((10240 + 64 * 136) * 4)

// ---------------- layer-2 elementwise epilogue -----------------------------------
__global__ void k_post(const float* __restrict__ y2x, const float* __restrict__ t2,
                       const float* __restrict__ b2,
                       float* __restrict__ x2, float* __restrict__ z) {
    int idx = blockIdx.x * blockDim.x + threadIdx.x;
    if (idx >= NN * 25) return;
    int n = idx / 25, q = idx - n * 25;
    float4 raw = ((const float4*)y2x)[(size_t)n * 64 + 32 + q];
    float4 tv = ((const float4*)t2)[idx];
    float4 bv = ((const float4*)b2)[q];
    float4 r1 = ((const float4*)x2)[idx];
    float4 r2 = ((const float4*)z)[idx];
    float v0 = fmaxf(raw.x + bv.x + tv.x, 0.f);
    float v1 = fmaxf(raw.y + bv.y + tv.y, 0.f);
    float v2 = fmaxf(raw.z + bv.z + tv.z, 0.f);
    float v3 = fmaxf(raw.w + bv.w + tv.w, 0.f);
    ((float4*)x2)[idx] = make_float4(v0 + r1.x, v1 + r1.y, v2 + r1.z, v3 + r1.w);
    ((float4*)z)[idx]  = make_float4(v0 + r2.x, v1 + r2.y, v2 + r2.z, v3 + r2.w);
}

// ---------------- tiny N=2 GEMM (layer 3) ----------------------------------------
__global__ void k_small2(const float* __restrict__ X, const float* __restrict__ W,
                         const float* __restrict__ bias, const float* __restrict__ add2,
                         float* __restrict__ out) {
    __shared__ float w[200];
    if (threadIdx.x < 200) w[threadIdx.x] = W[threadIdx.x];
    __syncthreads();
    int n = blockIdx.x * blockDim.x + threadIdx.x;
    if (n >= NN) return;
    const float4* xr = (const float4*)X + (size_t)n * 25;
    float s0 = 0.f, s1 = 0.f;
#pragma unroll
    for (int k = 0; k < 25; k++) {
        float4 v = xr[k];
        int b = 4 * k;
        s0 += v.x * w[(b + 0) * 2] + v.y * w[(b + 1) * 2] +
              v.z * w[(b + 2) * 2] + v.w * w[(b + 3) * 2];
        s1 += v.x * w[(b + 0) * 2 + 1] + v.y * w[(b + 1) * 2 + 1] +
              v.z * w[(b + 2) * 2 + 1] + v.w * w[(b + 3) * 2 + 1];
    }
    if (bias) { s0 += bias[0]; s1 += bias[1]; }
    if (add2) { s0 += add2[2 * n]; s1 += add2[2 * n + 1]; }
    out[2 * n] = s0;
    out[2 * n + 1] = s1;
}

// ---------------- link-prediction loss: 8 threads per pair, coalesced ------------
__global__ void k_loss(const int* __restrict__ ep, const int* __restrict__ en) {
    int gid = blockIdx.x * blockDim.x + threadIdx.x;
    int pair = gid >> 3;
    int sub = gid & 7;
    float term = 0.f;
    if (pair < 2 * PP) {
        int a, b;
        bool pos = (pair < PP);
        if (pos) { a = ep[pair]; b = ep[PP + pair]; }
        else { int j = pair - PP; a = en[j]; b = en[PP + j]; }
        const float4* za = (const float4*)g_z + (size_t)a * 25;
        const float4* zb = (const float4*)g_z + (size_t)b * 25;
        float s = 0.f;
#pragma unroll
        for (int k = sub; k < 25; k += 8) {
            float4 u = za[k], v = zb[k];
            s += u.x * v.x + u.y * v.y + u.z * v.z + u.w * v.w;
        }
        s += __shfl_down_sync(0xffffffff, s, 4);
        s += __shfl_down_sync(0xffffffff, s, 2);
        s += __shfl_down_sync(0xffffffff, s, 1);
        if (sub == 0) {
            float sig = 1.0f / (1.0f + expf(-s));
            float arg = pos ? (sig + 1e-15f) : (1.0f - sig + 1e-15f);
            term = logf(arg);
        }
    }
    __shared__ float red[256];
    red[threadIdx.x] = term;
    __syncthreads();
    for (int o = 128; o > 0; o >>= 1) {
        if (threadIdx.x < o) red[threadIdx.x] += red[threadIdx.x + o];
        __syncthreads();
    }
    if (threadIdx.x == 0) atomicAdd(&g_loss, red[0]);
}

__global__ void k_final(const float* __restrict__ c1, const float* __restrict__ c2,
                        float* __restrict__ out) {
    if (threadIdx.x == 0) {
        out[2 * NN + 0] = -g_loss / (float)PP;
        out[2 * NN + 1] = c1[0];
        out[2 * NN + 2] = c2[0];
    }
}

// ---------------- launch -----------------------------------------------------------
extern "C" void kernel_launch(void* const* d_in, const int* in_sizes, int n_in,
                              void* d_out, int out_size) {
    const float* x   = (const float*)d_in[0];
    const int*   ei  = (const int*)d_in[1];
    const int*   ep  = (const int*)d_in[2];
    const int*   en  = (const int*)d_in[3];
    const float* W1  = (const float*)d_in[4];
    const float* b1  = (const float*)d_in[5];
    const float* W2  = (const float*)d_in[6];
    const float* b2  = (const float*)d_in[7];
    const float* W3  = (const float*)d_in[8];
    const float* b3  = (const float*)d_in[9];
    const float* l1W = (const float*)d_in[10];
    const float* l1b = (const float*)d_in[11];
    const float* l2W = (const float*)d_in[12];
    const float* l2b = (const float*)d_in[13];
    const float* c1  = (const float*)d_in[14];
    const float* c2  = (const float*)d_in[15];
    float* out = (float*)d_out;

    static bool s_init = false;
    static cudaStream_t s1, s2;
    static cudaEvent_t evRoot, evConvX, evA, evS2, evZ, evSide;
    if (!s_init) {
        cudaFuncSetAttribute(k_bgemm<64>, cudaFuncAttributeMaxDynamicSharedMemorySize, SMEM64);
        cudaFuncSetAttribute(k_bgemm<128>, cudaFuncAttributeMaxDynamicSharedMemorySize, SMEM128);
        cudaStreamCreateWithFlags(&s1, cudaStreamNonBlocking);
        cudaStreamCreateWithFlags(&s2, cudaStreamNonBlocking);
        cudaEventCreateWithFlags(&evRoot, cudaEventDisableTiming);
        cudaEventCreateWithFlags(&evConvX, cudaEventDisableTiming);
        cudaEventCreateWithFlags(&evA, cudaEventDisableTiming);
        cudaEventCreateWithFlags(&evS2, cudaEventDisableTiming);
        cudaEventCreateWithFlags(&evZ, cudaEventDisableTiming);
        cudaEventCreateWithFlags(&evSide, cudaEventDisableTiming);
        s_init = true;
    }

    ushort_t *xh, *xl, *txh, *txl, *hh, *hl;
    ushort_t *w1h, *w1l, *w2h, *w2l, *l1h, *l1l, *l2h, *l2l;
    float *h1f, *y2x, *t2, *x2, *z, *y3, *t3;
    cudaGetSymbolAddress((void**)&xh, g_xh);   cudaGetSymbolAddress((void**)&xl, g_xl);
    cudaGetSymbolAddress((void**)&txh, g_txh); cudaGetSymbolAddress((void**)&txl, g_txl);
    cudaGetSymbolAddress((void**)&hh, g_hh);   cudaGetSymbolAddress((void**)&hl, g_hl);
    cudaGetSymbolAddress((void**)&w1h, g_w1h); cudaGetSymbolAddress((void**)&w1l, g_w1l);
    cudaGetSymbolAddress((void**)&w2h, g_w2h); cudaGetSymbolAddress((void**)&w2l, g_w2l);
    cudaGetSymbolAddress((void**)&l1h, g_l1h); cudaGetSymbolAddress((void**)&l1l, g_l1l);
    cudaGetSymbolAddress((void**)&l2h, g_l2h); cudaGetSymbolAddress((void**)&l2l, g_l2l);
    cudaGetSymbolAddress((void**)&h1f, g_h1f); cudaGetSymbolAddress((void**)&y2x, g_y2x);
    cudaGetSymbolAddress((void**)&t2, g_t2);
    cudaGetSymbolAddress((void**)&x2, g_x2);   cudaGetSymbolAddress((void**)&z, g_z);
    cudaGetSymbolAddress((void**)&y3, g_y3);   cudaGetSymbolAddress((void**)&t3, g_t3);

    // ---- fork side streams ----
    cudaEventRecord(evRoot, 0);
    cudaStreamWaitEvent(s1, evRoot, 0);
    cudaStreamWaitEvent(s2, evRoot, 0);

    // ---- s1: conv_x, conv W1 (padded to 384), layer-1 part A ----
    k_conv_x<<<(MP * 32 + 255) / 256, 256, 0, s1>>>(x);
    cudaEventRecord(evConvX, s1);
    k_conv_w<<<(128 * 384 + 255) / 256, 256, 0, s1>>>(W1, w1h, w1l, 128, 300, 128, 384, 0);
    k_conv_w<<<(128 * 384 + 255) / 256, 256, 0, s1>>>(W1 + 128 * 300, w1h + 128 * 384, w1l + 128 * 384, 128, 300, 128, 384, 0);
    k_conv_wc<<<(320 * 128 + 255) / 256, 256, 0, s1>>>(W2 + 300 * 100, w2h, w2l, 0);
    k_conv_wc<<<(320 * 128 + 255) / 256, 256, 0, s1>>>(W2, w2h, w2l, 128);
    // layer-1 part A: h1f = x@W1[0] + b1  (WN=128, grid.x=3)
    k_bgemm<128><<<dim3(3, MP / 128), 256, SMEM128, s1>>>(
        xh, xl, 128, w1h, w1l,
        nullptr, nullptr, 0, nullptr, nullptr,
        128, 0, 384, NN, 300,
        b1, nullptr, nullptr, nullptr, 0,
        h1f, nullptr, nullptr, nullptr, 300);
    cudaEventRecord(evA, s1);

    // ---- s2: conv lin, lin GEMMs ----
    k_conv_w<<<(128 * 128 + 255) / 256, 256, 0, s2>>>(l1W, l1h, l1l, 128, 100, 128, 128, 1);
    k_conv_w<<<(128 * 128 + 255) / 256, 256, 0, s2>>>(l2W, l2h, l2l, 128, 100, 128, 128, 1);
    cudaStreamWaitEvent(s2, evConvX, 0);
    k_bgemm<64><<<dim3(2, MP / 128), 256, SMEM64, s2>>>(
        xh, xl, 128, l1h, l1l,
        nullptr, nullptr, 0, nullptr, nullptr,
        128, 0, 128, NN, 100,
        l1b, nullptr, nullptr, nullptr, 1,
        x2, nullptr, nullptr, nullptr, 100);
    k_bgemm<64><<<dim3(2, MP / 128), 256, SMEM64, s2>>>(
        xh, xl, 128, l2h, l2l,
        nullptr, nullptr, 0, nullptr, nullptr,
        128, 0, 128, NN, 100,
        l2b, nullptr, nullptr, nullptr, 1,
        z, nullptr, nullptr, nullptr, 100);
    cudaEventRecord(evS2, s2);

    // ---- s0: graph preprocessing chain ----
    k_zero<<<(NN + 255) / 256, 256>>>();
    k_degcnt<<<(EE + 255) / 256, 256>>>(ei);
    k_dinv<<<(NN + 255) / 256, 256>>>();
    k_scan1<<<NB_SCAN, 256>>>();
    k_scan2<<<1, 256>>>();
    k_scan3<<<NB_SCAN, 256>>>();
    k_fill<<<(EE + 255) / 256, 256>>>(ei);
    k_zero_hpad<<<((MP - NN) * 320 + 255) / 256, 256>>>();

    // ---- s0: gather, then layer-1 part B: h = relu(tx1@W1[1] + h1f) -> hh/hl ----
    k_gather128bf<<<(MP * 32 + 255) / 256, 256>>>(x);
    cudaStreamWaitEvent(0, evA, 0);
    k_bgemm<128><<<dim3(3, MP / 128), 256, SMEM128>>>(
        txh, txl, 128, w1h + 128 * 384, w1l + 128 * 384,
        nullptr, nullptr, 0, nullptr, nullptr,
        128, 0, 384, NN, 300,
        nullptr, h1f, nullptr, nullptr, 1,
        nullptr, nullptr, hh, hl, 320);

    // ---- s0: layer 2 combined GEMM (WN=128): y2x = h @ [W2[1] | W2[0]] ----
    cudaStreamWaitEvent(0, evS2, 0);
    k_bgemm<128><<<dim3(2, MP / 128), 256, SMEM128>>>(
        hh, hl, 320, w2h, w2l,
        nullptr, nullptr, 0, nullptr, nullptr,
        320, 0, 256, NN, 256,
        nullptr, nullptr, nullptr, nullptr, 0,
        y2x, nullptr, nullptr, nullptr, 256);
    k_gather<25, 64><<<(NN * 32 + 255) / 256, 256>>>(y2x, t2);
    k_post<<<(NN * 25 + 255) / 256, 256>>>(y2x, t2, b2, x2, z);
    cudaEventRecord(evZ, 0);

    // ---- s0: layer 3 output chain ----
    k_small2<<<(NN + 255) / 256, 256>>>(x2, W3 + 200, nullptr, nullptr, y3);
    k_gather2<<<(NN + 255) / 256, 256>>>(y3, t3);
    k_small2<<<(NN + 255) / 256, 256>>>(x2, W3, b3, t3, out);

    // ---- s1: loss chain, concurrent with layer 3 ----
    cudaStreamWaitEvent(s1, evZ, 0);
    k_loss<<<(2 * PP * 8 + 255) / 256, 256, 0, s1>>>(ep, en);
    k_final<<<1, 32, 0, s1>>>(c1, c2, out);
    cudaEventRecord(evSide, s1);

    // ---- join ----
    cudaStreamWaitEvent(0, evSide, 0);
}

// round 12
// speedup vs baseline: 1.0822x; 1.0822x over previous
#include <cuda_runtime.h>
#include <cuda_bf16.h>
#include <math.h>

#define NN 50000
#define MP 50048          // NN padded to 128
#define EE 800000
#define PP 400000
#define NB_SCAN 196       // ceil(NN/256)
#define CHUNK0 25088      // 196*128
#define CHUNK1 (MP - CHUNK0)  // 24960 = 195*128

typedef unsigned short ushort_t;
typedef unsigned int uint_t;

// ---------------- scratch (device globals) ----------------------------------
static __device__ __align__(16) ushort_t g_xh[MP * 128];
static __device__ __align__(16) ushort_t g_xl[MP * 128];
static __device__ __align__(16) ushort_t g_txh[MP * 128];
static __device__ __align__(16) ushort_t g_txl[MP * 128];
static __device__ __align__(16) ushort_t g_hh[MP * 320];
static __device__ __align__(16) ushort_t g_hl[MP * 320];
static __device__ __align__(16) ushort_t g_w1h[2 * 128 * 320];
static __device__ __align__(16) ushort_t g_w1l[2 * 128 * 320];
static __device__ __align__(16) ushort_t g_w2h[320 * 256];   // cat: [W2[1] | W2[0]]
static __device__ __align__(16) ushort_t g_w2l[320 * 256];
static __device__ __align__(16) ushort_t g_l1h[128 * 128];
static __device__ __align__(16) ushort_t g_l1l[128 * 128];
static __device__ __align__(16) ushort_t g_l2h[128 * 128];
static __device__ __align__(16) ushort_t g_l2l[128 * 128];

static __device__ __align__(16) float g_h1f[NN * 300];       // x@W1[0]+b1 (fp32)
static __device__ __align__(16) float g_y2x[MP * 256];       // [y2 | x1raw]
static __device__ __align__(16) float g_t2[NN * 100];
static __device__ __align__(16) float g_x2[NN * 100];
static __device__ __align__(16) float g_z[NN * 100];
static __device__ __align__(16) float g_y3[NN * 2];
static __device__ __align__(16) float g_t3[NN * 2];
static __device__ float g_dinv[NN];
static __device__ int   g_deg[NN];
static __device__ int   g_cnt[NN];
static __device__ int   g_fill[NN];
static __device__ int   g_rowptr[NN + 1];
static __device__ int   g_bsum[NB_SCAN];
static __device__ int   g_boff[NB_SCAN];
static __device__ int   g_csr_src[EE];
static __device__ float g_csr_w[EE];
static __device__ float g_loss;

// ---------------- helpers ----------------------------------------------------
__device__ __forceinline__ void split1(float v, ushort_t& h, ushort_t& l) {
    __nv_bfloat16 bh = __float2bfloat16_rn(v);
    h = __bfloat16_as_ushort(bh);
    float r = v - __bfloat162float(bh);
    l = __bfloat16_as_ushort(__float2bfloat16_rn(r));
}

__device__ __forceinline__ void ldsm4(uint_t* r, uint_t addr) {
    asm volatile("ldmatrix.sync.aligned.m8n8.x4.shared.b16 {%0,%1,%2,%3}, [%4];"
                 : "=r"(r[0]), "=r"(r[1]), "=r"(r[2]), "=r"(r[3]) : "r"(addr));
}
__device__ __forceinline__ void ldsm4t(uint_t* r, uint_t addr) {
    asm volatile("ldmatrix.sync.aligned.m8n8.x4.trans.shared.b16 {%0,%1,%2,%3}, [%4];"
                 : "=r"(r[0]), "=r"(r[1]), "=r"(r[2]), "=r"(r[3]) : "r"(addr));
}
__device__ __forceinline__ void mma_bf16(float* d, const uint_t* a, uint_t b0, uint_t b1) {
    asm volatile(
        "mma.sync.aligned.m16n8k16.row.col.f32.bf16.bf16.f32 "
        "{%0,%1,%2,%3},{%4,%5,%6,%7},{%8,%9},{%0,%1,%2,%3};"
        : "+f"(d[0]), "+f"(d[1]), "+f"(d[2]), "+f"(d[3])
        : "r"(a[0]), "r"(a[1]), "r"(a[2]), "r"(a[3]), "r"(b0), "r"(b1));
}
__device__ __forceinline__ void cp16(uint_t dst, const void* src) {
    asm volatile("cp.async.cg.shared.global [%0], [%1], 16;\n" :: "r"(dst), "l"(src));
}

// ---------------- graph preprocessing ----------------------------------------
__global__ void k_zero() {
    int i = blockIdx.x * blockDim.x + threadIdx.x;
    if (i < NN) { g_deg[i] = 0; g_cnt[i] = 0; g_fill[i] = 0; }
    if (i == 0) g_loss = 0.0f;
}

__global__ void k_degcnt(const int* __restrict__ ei) {
    int e = blockIdx.x * blockDim.x + threadIdx.x;
    if (e < EE) {
        atomicAdd(&g_deg[ei[e]], 1);
        atomicAdd(&g_cnt[ei[EE + e]], 1);
    }
}

__global__ void k_dinv() {
    int i = blockIdx.x * blockDim.x + threadIdx.x;
    if (i < NN) {
        int d = g_deg[i];
        g_dinv[i] = (d > 0) ? rsqrtf((float)d) : 0.0f;
    }
}

__global__ void k_scan1() {
    __shared__ int s[256];
    int t = threadIdx.x;
    int i = blockIdx.x * 256 + t;
    s[t] = (i < NN) ? g_cnt[i] : 0;
    __syncthreads();
    for (int o = 128; o > 0; o >>= 1) {
        if (t < o) s[t] += s[t + o];
        __syncthreads();
    }
    if (t == 0) g_bsum[blockIdx.x] = s[0];
}

__global__ void k_scan2() {
    __shared__ int s[256];
    int t = threadIdx.x;
    int v = (t < NB_SCAN) ? g_bsum[t] : 0;
    s[t] = v;
    __syncthreads();
    for (int o = 1; o < 256; o <<= 1) {
        int tv = (t >= o) ? s[t - o] : 0;
        __syncthreads();
        s[t] += tv;
        __syncthreads();
    }
    if (t < NB_SCAN) g_boff[t] = s[t] - v;
    if (t == 255) g_rowptr[NN] = s[255];
}

__global__ void k_scan3() {
    __shared__ int s[256];
    int t = threadIdx.x;
    int i = blockIdx.x * 256 + t;
    int v = (i < NN) ? g_cnt[i] : 0;
    s[t] = v;
    __syncthreads();
    for (int o = 1; o < 256; o <<= 1) {
        int tv = (t >= o) ? s[t - o] : 0;
        __syncthreads();
        s[t] += tv;
        __syncthreads();
    }
    if (i < NN) g_rowptr[i] = g_boff[blockIdx.x] + s[t] - v;
}

__global__ void k_fill(const int* __restrict__ ei) {
    int e = blockIdx.x * blockDim.x + threadIdx.x;
    if (e < EE) {
        int s = ei[e];
        int d = ei[EE + e];
        int pos = g_rowptr[d] + atomicAdd(&g_fill[d], 1);
        g_csr_src[pos] = s;
        g_csr_w[pos] = -g_dinv[s] * g_dinv[d];
    }
}

// ---------------- conversions --------------------------------------------------
__global__ void k_conv_x(const float* __restrict__ x) {
    int idx = blockIdx.x * blockDim.x + threadIdx.x;
    if (idx >= MP * 32) return;
    int row = idx >> 5;
    float4 v = (row < NN) ? ((const float4*)x)[idx] : make_float4(0.f, 0.f, 0.f, 0.f);
    ushort_t h0, h1, h2, h3, l0, l1, l2, l3;
    split1(v.x, h0, l0); split1(v.y, h1, l1);
    split1(v.z, h2, l2); split1(v.w, h3, l3);
    ((uint2*)g_xh)[idx] = make_uint2((uint_t)h0 | ((uint_t)h1 << 16), (uint_t)h2 | ((uint_t)h3 << 16));
    ((uint2*)g_xl)[idx] = make_uint2((uint_t)l0 | ((uint_t)l1 << 16), (uint_t)l2 | ((uint_t)l3 << 16));
}

__global__ void k_conv_w(const float* __restrict__ src, ushort_t* __restrict__ dh,
                         ushort_t* __restrict__ dl, int K, int N, int Kp, int Np, int trans) {
    int idx = blockIdx.x * blockDim.x + threadIdx.x;
    if (idx >= Kp * Np) return;
    int k = idx / Np, n = idx % Np;
    float v = 0.f;
    if (k < K && n < N) v = trans ? src[n * K + k] : src[k * N + n];
    ushort_t h, l;
    split1(v, h, l);
    dh[idx] = h;
    dl[idx] = l;
}

// W2 concatenated conversion: src [300,100] -> dst[320,256] cols [coff, coff+128)
__global__ void k_conv_wc(const float* __restrict__ src, ushort_t* __restrict__ dh,
                          ushort_t* __restrict__ dl, int coff) {
    int idx = blockIdx.x * blockDim.x + threadIdx.x;
    if (idx >= 320 * 128) return;
    int k = idx >> 7, n = idx & 127;
    float v = (k < 300 && n < 100) ? src[k * 100 + n] : 0.f;
    ushort_t h, l;
    split1(v, h, l);
    dh[k * 256 + coff + n] = h;
    dl[k * 256 + coff + n] = l;
}

__global__ void k_zero_hpad() {
    int idx = blockIdx.x * blockDim.x + threadIdx.x;
    if (idx < (MP - NN) * 320) {
        g_hh[(size_t)NN * 320 + idx] = 0;
        g_hl[(size_t)NN * 320 + idx] = 0;
    }
}

// ---------------- gathers -------------------------------------------------------
// row-chunked gather of x into bf16 hi/lo split
__global__ void k_gather128bf(const float* __restrict__ x, int rowBeg, int nRows) {
    int g0 = (blockIdx.x * blockDim.x + threadIdx.x) >> 5;
    int lane = threadIdx.x & 31;
    if (g0 >= nRows) return;
    int gw = rowBeg + g0;
    float4 acc = make_float4(0.f, 0.f, 0.f, 0.f);
    if (gw < NN) {
        int beg = g_rowptr[gw], end = g_rowptr[gw + 1];
        const float4* sf = (const float4*)x;
        for (int e = beg; e < end; e++) {
            int s = g_csr_src[e];
            float w = g_csr_w[e];
            float4 v = sf[(size_t)s * 32 + lane];
            acc.x += w * v.x; acc.y += w * v.y;
            acc.z += w * v.z; acc.w += w * v.w;
        }
    }
    ushort_t h0, h1, h2, h3, l0, l1, l2, l3;
    split1(acc.x, h0, l0); split1(acc.y, h1, l1);
    split1(acc.z, h2, l2); split1(acc.w, h3, l3);
    size_t idx = (size_t)gw * 32 + lane;
    ((uint2*)g_txh)[idx] = make_uint2((uint_t)h0 | ((uint_t)h1 << 16), (uint_t)h2 | ((uint_t)h3 << 16));
    ((uint2*)g_txl)[idx] = make_uint2((uint_t)l0 | ((uint_t)l1 << 16), (uint_t)l2 | ((uint_t)l3 << 16));
}

template <int F4, int LD4>
__global__ void k_gather(const float* __restrict__ SF, float* __restrict__ DF) {
    int gw = (blockIdx.x * blockDim.x + threadIdx.x) >> 5;
    int lane = threadIdx.x & 31;
    if (gw >= NN) return;
    int beg = g_rowptr[gw], end = g_rowptr[gw + 1];
    if (lane < F4) {
        const float4* sf = (const float4*)SF;
        float4 acc = make_float4(0.f, 0.f, 0.f, 0.f);
        for (int e = beg; e < end; e++) {
            int s = g_csr_src[e];
            float w = g_csr_w[e];
            float4 v = sf[(size_t)s * LD4 + lane];
            acc.x += w * v.x; acc.y += w * v.y;
            acc.z += w * v.z; acc.w += w * v.w;
        }
        ((float4*)DF)[(size_t)gw * F4 + lane] = acc;
    }
}

__global__ void k_gather2(const float* __restrict__ SF, float* __restrict__ DF) {
    int n = blockIdx.x * blockDim.x + threadIdx.x;
    if (n >= NN) return;
    int beg = g_rowptr[n], end = g_rowptr[n + 1];
    float a0 = 0.f, a1 = 0.f;
    for (int e = beg; e < end; e++) {
        int s = g_csr_src[e];
        float w = g_csr_w[e];
        a0 += w * SF[2 * s];
        a1 += w * SF[2 * s + 1];
    }
    DF[2 * n] = a0;
    DF[2 * n + 1] = a1;
}

// ---------------- bf16x3 tensor-core GEMM, 2-stage cp.async, WN-templated -------
// CTA tile 128 x WN; 8 warps (4x2); warp tile 32 x (WN/2).
#define A_L_OFF 5120

template <int WN>
__device__ __forceinline__ void issue_tile(
    uint_t sbase, int tid,
    const ushort_t* __restrict__ Ah, const ushort_t* __restrict__ Al, int lda, int rowBase,
    const ushort_t* __restrict__ Bh, const ushort_t* __restrict__ Bl, int ldb, int colBase,
    int k0) {
    constexpr int BST = WN + 8;
    constexpr int B_H_OFFt = 10240;
    constexpr int B_L_OFFt = 10240 + 32 * BST;
    constexpr int BCH = WN / 8;          // 16B chunks per B row
#pragma unroll
    for (int i = 0; i < 4; i++) {
        int idx = tid + i * 256;
        int arr = idx >> 9, rem = idx & 511;
        int row = rem >> 2, ch = rem & 3;
        const ushort_t* src = (arr ? Al : Ah) + (size_t)(rowBase + row) * lda + k0 + ch * 8;
        uint_t dst = sbase + (uint_t)((arr ? A_L_OFF : 0) + row * 40 + ch * 8) * 2;
        cp16(dst, src);
    }
    constexpr int BTOT = 2 * 32 * BCH;   // total B chunks (hi+lo)
#pragma unroll
    for (int i = 0; i < BTOT / 256; i++) {
        int idx = tid + i * 256;
        int arr = (idx >= 32 * BCH) ? 1 : 0;
        int rem = idx - arr * 32 * BCH;
        int row = rem / BCH, ch = rem % BCH;
        const ushort_t* src = (arr ? Bl : Bh) + (size_t)(k0 + row) * ldb + colBase + ch * 8;
        uint_t dst = sbase + (uint_t)((arr ? B_L_OFFt : B_H_OFFt) + row * BST + ch * 8) * 2;
        cp16(dst, src);
    }
    asm volatile("cp.async.commit_group;\n");
}

template <int WN>
__global__ __launch_bounds__(256)
void k_bgemm(const ushort_t* __restrict__ Ah1, const ushort_t* __restrict__ Al1, int lda1,
             const ushort_t* __restrict__ Bh1, const ushort_t* __restrict__ Bl1,
             const ushort_t* __restrict__ Ah2, const ushort_t* __restrict__ Al2, int lda2,
             const ushort_t* __restrict__ Bh2, const ushort_t* __restrict__ Bl2,
             int K1, int K2, int ldb, int rowOff,
             int M, int N,
             const float* __restrict__ bias, const float* __restrict__ addend,
             const float* __restrict__ post1, const float* __restrict__ post2, int relu,
             float* __restrict__ Cf1, float* __restrict__ Cf2,
             ushort_t* __restrict__ Ch, ushort_t* __restrict__ Cl,
             int ldc) {
    constexpr int BST = WN + 8;
    constexpr int B_H_OFFt = 10240;
    constexpr int STAGE = 10240 + 64 * BST;
    constexpr int NP = WN / 32;          // 16-wide B fragments per warp
    constexpr int NREG = WN / 16;        // 8-wide accum groups per warp

    extern __shared__ __align__(16) ushort_t sm[];
    uint_t sbase0 = (uint_t)__cvta_generic_to_shared(sm);

    int tid = threadIdx.x, lane = tid & 31, wid = tid >> 5;
    int warp_m = wid & 3, warp_n = wid >> 2;
    int rowBase = rowOff + blockIdx.y * 128, colBase = blockIdx.x * WN;

    float acc[2][NREG][4];
#pragma unroll
    for (int m = 0; m < 2; m++)
#pragma unroll
        for (int n = 0; n < NREG; n++)
#pragma unroll
            for (int q = 0; q < 4; q++) acc[m][n][q] = 0.f;

    int T1 = K1 / 32;
    int T2 = (Ah2 != nullptr) ? (K2 / 32) : 0;
    int T = T1 + T2;

#define ISSUE(t)                                                                          \
    do {                                                                                  \
        int _t = (t);                                                                     \
        uint_t _sb = sbase0 + (uint_t)((_t & 1) * STAGE) * 2;                             \
        if (_t < T1)                                                                      \
            issue_tile<WN>(_sb, tid, Ah1, Al1, lda1, rowBase, Bh1, Bl1, ldb, colBase, _t * 32); \
        else                                                                              \
            issue_tile<WN>(_sb, tid, Ah2, Al2, lda2, rowBase, Bh2, Bl2, ldb, colBase, (_t - T1) * 32); \
    } while (0)

    ISSUE(0);

    for (int t = 0; t < T; t++) {
        if (t + 1 < T) {
            ISSUE(t + 1);
            asm volatile("cp.async.wait_group 1;\n");
        } else {
            asm volatile("cp.async.wait_group 0;\n");
        }
        __syncthreads();

        uint_t sA = sbase0 + (uint_t)((t & 1) * STAGE) * 2;
        uint_t sB = sA + (uint_t)B_H_OFFt * 2;

#pragma unroll
        for (int kk = 0; kk < 32; kk += 16) {
            uint_t ah[2][4], al[2][4], bh[NP][4], bl[NP][4];
            int g = lane >> 3, r = lane & 7;
#pragma unroll
            for (int m = 0; m < 2; m++) {
                int arow = warp_m * 32 + m * 16 + r + (g & 1) * 8;
                int acol = kk + (g >> 1) * 8;
                uint_t off = (uint_t)(arow * 40 + acol) * 2;
                ldsm4(ah[m], sA + off);
                ldsm4(al[m], sA + (uint_t)A_L_OFF * 2 + off);
            }
#pragma unroll
            for (int np = 0; np < NP; np++) {
                int brow = kk + r + (g & 1) * 8;
                int bcol = warp_n * (WN / 2) + np * 16 + (g >> 1) * 8;
                uint_t off = (uint_t)(brow * BST + bcol) * 2;
                ldsm4t(bh[np], sB + off);
                ldsm4t(bl[np], sB + (uint_t)(32 * BST) * 2 + off);
            }
#pragma unroll
            for (int m = 0; m < 2; m++)
#pragma unroll
                for (int n = 0; n < NREG; n++) {
                    uint_t b0h = bh[n >> 1][(n & 1) * 2], b1h = bh[n >> 1][(n & 1) * 2 + 1];
                    uint_t b0l = bl[n >> 1][(n & 1) * 2], b1l = bl[n >> 1][(n & 1) * 2 + 1];
                    mma_bf16(acc[m][n], ah[m], b0h, b1h);  // hi*hi
                    mma_bf16(acc[m][n], ah[m], b0l, b1l);  // hi*lo
                    mma_bf16(acc[m][n], al[m], b0h, b1h);  // lo*hi
                }
        }
        __syncthreads();
    }
#undef ISSUE

    // epilogue
#pragma unroll
    for (int m = 0; m < 2; m++)
#pragma unroll
        for (int n = 0; n < NREG; n++) {
#pragma unroll
            for (int half = 0; half < 2; half++) {
                float v0 = acc[m][n][half * 2 + 0];
                float v1 = acc[m][n][half * 2 + 1];
                int gr = rowBase + warp_m * 32 + m * 16 + (lane >> 2) + half * 8;
                int gc = colBase + warp_n * (WN / 2) + n * 8 + (lane & 3) * 2;
                if (gr >= M || gc >= N) continue;
                if (bias) { v0 += bias[gc]; v1 += bias[gc + 1]; }
                if (addend) {
                    v0 += addend[(size_t)gr * N + gc];
                    v1 += addend[(size_t)gr * N + gc + 1];
                }
                if (relu) { v0 = fmaxf(v0, 0.f); v1 = fmaxf(v1, 0.f); }
                size_t oidx = (size_t)gr * ldc + gc;
                if (Cf1) {
                    float a0 = v0, a1 = v1;
                    if (post1) {
                        float2 p = *(const float2*)&post1[oidx];
                        a0 += p.x; a1 += p.y;
                    }
                    float2 o; o.x = a0; o.y = a1;
                    *(float2*)&Cf1[oidx] = o;
                }
                if (Cf2) {
                    float a0 = v0, a1 = v1;
                    if (post2) {
                        float2 p = *(const float2*)&post2[oidx];
                        a0 += p.x; a1 += p.y;
                    }
                    float2 o; o.x = a0; o.y = a1;
                    *(float2*)&Cf2[oidx] = o;
                }
                if (Ch) {
                    ushort_t h0, l0, h1, l1;
                    split1(v0, h0, l0);
                    split1(v1, h1, l1);
                    *(uint_t*)&Ch[oidx] = (uint_t)h0 | ((uint_t)h1 << 16);
                    *(uint_t*)&Cl[oidx] = (uint_t)l0 | ((uint_t)l1 << 16);
                }
            }
        }
}

#define SMEM64  ((10240 + 64 * 72) * 4)
#define SMEM128 ((10240 + 64 * 136) * 4)

// ---------------- layer-2 elementwise epilogue -----------------------------------
__global__ void k_post(const float* __restrict__ y2x, const float* __restrict__ t2,
                       const float* __restrict__ b2,
                       float* __restrict__ x2, float* __restrict__ z) {
    int idx = blockIdx.x * blockDim.x + threadIdx.x;
    if (idx >= NN * 25) return;
    int n = idx / 25, q = idx - n * 25;
    float4 raw = ((const float4*)y2x)[(size_t)n * 64 + 32 + q];
    float4 tv = ((const float4*)t2)[idx];
    float4 bv = ((const float4*)b2)[q];
    float4 r1 = ((const float4*)x2)[idx];
    float4 r2 = ((const float4*)z)[idx];
    float v0 = fmaxf(raw.x + bv.x + tv.x, 0.f);
    float v1 = fmaxf(raw.y + bv.y + tv.y, 0.f);
    float v2 = fmaxf(raw.z + bv.z + tv.z, 0.f);
    float v3 = fmaxf(raw.w + bv.w + tv.w, 0.f);
    ((float4*)x2)[idx] = make_float4(v0 + r1.x, v1 + r1.y, v2 + r1.z, v3 + r1.w);
    ((float4*)z)[idx]  = make_float4(v0 + r2.x, v1 + r2.y, v2 + r2.z, v3 + r2.w);
}

// ---------------- tiny N=2 GEMM (layer 3) ----------------------------------------
__global__ void k_small2(const float* __restrict__ X, const float* __restrict__ W,
                         const float* __restrict__ bias, const float* __restrict__ add2,
                         float* __restrict__ out) {
    __shared__ float w[200];
    if (threadIdx.x < 200) w[threadIdx.x] = W[threadIdx.x];
    __syncthreads();
    int n = blockIdx.x * blockDim.x + threadIdx.x;
    if (n >= NN) return;
    const float4* xr = (const float4*)X + (size_t)n * 25;
    float s0 = 0.f, s1 = 0.f;
#pragma unroll
    for (int k = 0; k < 25; k++) {
        float4 v = xr[k];
        int b = 4 * k;
        s0 += v.x * w[(b + 0) * 2] + v.y * w[(b + 1) * 2] +
              v.z * w[(b + 2) * 2] + v.w * w[(b + 3) * 2];
        s1 += v.x * w[(b + 0) * 2 + 1] + v.y * w[(b + 1) * 2 + 1] +
              v.z * w[(b + 2) * 2 + 1] + v.w * w[(b + 3) * 2 + 1];
    }
    if (bias) { s0 += bias[0]; s1 += bias[1]; }
    if (add2) { s0 += add2[2 * n]; s1 += add2[2 * n + 1]; }
    out[2 * n] = s0;
    out[2 * n + 1] = s1;
}

// ---------------- link-prediction loss: 8 threads per pair, coalesced ------------
__global__ void k_loss(const int* __restrict__ ep, const int* __restrict__ en) {
    int gid = blockIdx.x * blockDim.x + threadIdx.x;
    int pair = gid >> 3;
    int sub = gid & 7;
    float term = 0.f;
    if (pair < 2 * PP) {
        int a, b;
        bool pos = (pair < PP);
        if (pos) { a = ep[pair]; b = ep[PP + pair]; }
        else { int j = pair - PP; a = en[j]; b = en[PP + j]; }
        const float4* za = (const float4*)g_z + (size_t)a * 25;
        const float4* zb = (const float4*)g_z + (size_t)b * 25;
        float s = 0.f;
#pragma unroll
        for (int k = sub; k < 25; k += 8) {
            float4 u = za[k], v = zb[k];
            s += u.x * v.x + u.y * v.y + u.z * v.z + u.w * v.w;
        }
        s += __shfl_down_sync(0xffffffff, s, 4);
        s += __shfl_down_sync(0xffffffff, s, 2);
        s += __shfl_down_sync(0xffffffff, s, 1);
        if (sub == 0) {
            float sig = 1.0f / (1.0f + expf(-s));
            float arg = pos ? (sig + 1e-15f) : (1.0f - sig + 1e-15f);
            term = logf(arg);
        }
    }
    __shared__ float red[256];
    red[threadIdx.x] = term;
    __syncthreads();
    for (int o = 128; o > 0; o >>= 1) {
        if (threadIdx.x < o) red[threadIdx.x] += red[threadIdx.x + o];
        __syncthreads();
    }
    if (threadIdx.x == 0) atomicAdd(&g_loss, red[0]);
}

__global__ void k_final(const float* __restrict__ c1, const float* __restrict__ c2,
                        float* __restrict__ out) {
    if (threadIdx.x == 0) {
        out[2 * NN + 0] = -g_loss / (float)PP;
        out[2 * NN + 1] = c1[0];
        out[2 * NN + 2] = c2[0];
    }
}

// ---------------- launch -----------------------------------------------------------
extern "C" void kernel_launch(void* const* d_in, const int* in_sizes, int n_in,
                              void* d_out, int out_size) {
    const float* x   = (const float*)d_in[0];
    const int*   ei  = (const int*)d_in[1];
    const int*   ep  = (const int*)d_in[2];
    const int*   en  = (const int*)d_in[3];
    const float* W1  = (const float*)d_in[4];
    const float* b1  = (const float*)d_in[5];
    const float* W2  = (const float*)d_in[6];
    const float* b2  = (const float*)d_in[7];
    const float* W3  = (const float*)d_in[8];
    const float* b3  = (const float*)d_in[9];
    const float* l1W = (const float*)d_in[10];
    const float* l1b = (const float*)d_in[11];
    const float* l2W = (const float*)d_in[12];
    const float* l2b = (const float*)d_in[13];
    const float* c1  = (const float*)d_in[14];
    const float* c2  = (const float*)d_in[15];
    float* out = (float*)d_out;

    static bool s_init = false;
    static cudaStream_t s1, s2;
    static cudaEvent_t evRoot, evConvX, evA, evS2, evZ, evSide, evFill, evB1;
    if (!s_init) {
        cudaFuncSetAttribute(k_bgemm<64>, cudaFuncAttributeMaxDynamicSharedMemorySize, SMEM64);
        cudaFuncSetAttribute(k_bgemm<128>, cudaFuncAttributeMaxDynamicSharedMemorySize, SMEM128);
        cudaStreamCreateWithFlags(&s1, cudaStreamNonBlocking);
        cudaStreamCreateWithFlags(&s2, cudaStreamNonBlocking);
        cudaEventCreateWithFlags(&evRoot, cudaEventDisableTiming);
        cudaEventCreateWithFlags(&evConvX, cudaEventDisableTiming);
        cudaEventCreateWithFlags(&evA, cudaEventDisableTiming);
        cudaEventCreateWithFlags(&evS2, cudaEventDisableTiming);
        cudaEventCreateWithFlags(&evZ, cudaEventDisableTiming);
        cudaEventCreateWithFlags(&evSide, cudaEventDisableTiming);
        cudaEventCreateWithFlags(&evFill, cudaEventDisableTiming);
        cudaEventCreateWithFlags(&evB1, cudaEventDisableTiming);
        s_init = true;
    }

    ushort_t *xh, *xl, *txh, *txl, *hh, *hl;
    ushort_t *w1h, *w1l, *w2h, *w2l, *l1h, *l1l, *l2h, *l2l;
    float *h1f, *y2x, *t2, *x2, *z, *y3, *t3;
    cudaGetSymbolAddress((void**)&xh, g_xh);   cudaGetSymbolAddress((void**)&xl, g_xl);
    cudaGetSymbolAddress((void**)&txh, g_txh); cudaGetSymbolAddress((void**)&txl, g_txl);
    cudaGetSymbolAddress((void**)&hh, g_hh);   cudaGetSymbolAddress((void**)&hl, g_hl);
    cudaGetSymbolAddress((void**)&w1h, g_w1h); cudaGetSymbolAddress((void**)&w1l, g_w1l);
    cudaGetSymbolAddress((void**)&w2h, g_w2h); cudaGetSymbolAddress((void**)&w2l, g_w2l);
    cudaGetSymbolAddress((void**)&l1h, g_l1h); cudaGetSymbolAddress((void**)&l1l, g_l1l);
    cudaGetSymbolAddress((void**)&l2h, g_l2h); cudaGetSymbolAddress((void**)&l2l, g_l2l);
    cudaGetSymbolAddress((void**)&h1f, g_h1f); cudaGetSymbolAddress((void**)&y2x, g_y2x);
    cudaGetSymbolAddress((void**)&t2, g_t2);
    cudaGetSymbolAddress((void**)&x2, g_x2);   cudaGetSymbolAddress((void**)&z, g_z);
    cudaGetSymbolAddress((void**)&y3, g_y3);   cudaGetSymbolAddress((void**)&t3, g_t3);

    // ---- fork side streams ----
    cudaEventRecord(evRoot, 0);
    cudaStreamWaitEvent(s1, evRoot, 0);
    cudaStreamWaitEvent(s2, evRoot, 0);

    // ---- s1: conv_x, conv W1/W2, layer-1 part A ----
    k_conv_x<<<(MP * 32 + 255) / 256, 256, 0, s1>>>(x);
    cudaEventRecord(evConvX, s1);
    k_conv_w<<<(128 * 320 + 255) / 256, 256, 0, s1>>>(W1, w1h, w1l, 128, 300, 128, 320, 0);
    k_conv_w<<<(128 * 320 + 255) / 256, 256, 0, s1>>>(W1 + 128 * 300, w1h + 128 * 320, w1l + 128 * 320, 128, 300, 128, 320, 0);
    k_conv_wc<<<(320 * 128 + 255) / 256, 256, 0, s1>>>(W2 + 300 * 100, w2h, w2l, 0);
    k_conv_wc<<<(320 * 128 + 255) / 256, 256, 0, s1>>>(W2, w2h, w2l, 128);
    // layer-1 part A: h1f = x@W1[0] + b1  (WN=64, grid.x=5)
    k_bgemm<64><<<dim3(5, MP / 128), 256, SMEM64, s1>>>(
        xh, xl, 128, w1h, w1l,
        nullptr, nullptr, 0, nullptr, nullptr,
        128, 0, 320, 0, NN, 300,
        b1, nullptr, nullptr, nullptr, 0,
        h1f, nullptr, nullptr, nullptr, 300);
    cudaEventRecord(evA, s1);

    // ---- s2: conv lin, lin GEMMs ----
    k_conv_w<<<(128 * 128 + 255) / 256, 256, 0, s2>>>(l1W, l1h, l1l, 128, 100, 128, 128, 1);
    k_conv_w<<<(128 * 128 + 255) / 256, 256, 0, s2>>>(l2W, l2h, l2l, 128, 100, 128, 128, 1);
    cudaStreamWaitEvent(s2, evConvX, 0);
    k_bgemm<64><<<dim3(2, MP / 128), 256, SMEM64, s2>>>(
        xh, xl, 128, l1h, l1l,
        nullptr, nullptr, 0, nullptr, nullptr,
        128, 0, 128, 0, NN, 100,
        l1b, nullptr, nullptr, nullptr, 1,
        x2, nullptr, nullptr, nullptr, 100);
    k_bgemm<64><<<dim3(2, MP / 128), 256, SMEM64, s2>>>(
        xh, xl, 128, l2h, l2l,
        nullptr, nullptr, 0, nullptr, nullptr,
        128, 0, 128, 0, NN, 100,
        l2b, nullptr, nullptr, nullptr, 1,
        z, nullptr, nullptr, nullptr, 100);
    cudaEventRecord(evS2, s2);

    // ---- s0: graph preprocessing chain ----
    k_zero<<<(NN + 255) / 256, 256>>>();
    k_degcnt<<<(EE + 255) / 256, 256>>>(ei);
    k_dinv<<<(NN + 255) / 256, 256>>>();
    k_scan1<<<NB_SCAN, 256>>>();
    k_scan2<<<1, 256>>>();
    k_scan3<<<NB_SCAN, 256>>>();
    k_fill<<<(EE + 255) / 256, 256>>>(ei);
    cudaEventRecord(evFill, 0);
    k_zero_hpad<<<((MP - NN) * 320 + 255) / 256, 256>>>();

    // ---- chunked gather + part-B pipeline ----
    // s0: chunk 0 (rows 0..CHUNK0)
    k_gather128bf<<<(CHUNK0 * 32) / 256, 256>>>(x, 0, CHUNK0);
    cudaStreamWaitEvent(0, evA, 0);
    k_bgemm<64><<<dim3(5, CHUNK0 / 128), 256, SMEM64>>>(
        txh, txl, 128, w1h + 128 * 320, w1l + 128 * 320,
        nullptr, nullptr, 0, nullptr, nullptr,
        128, 0, 320, 0, NN, 300,
        nullptr, h1f, nullptr, nullptr, 1,
        nullptr, nullptr, hh, hl, 320);
    // s1: chunk 1 (rows CHUNK0..MP) — s1 is free after part A
    cudaStreamWaitEvent(s1, evFill, 0);
    k_gather128bf<<<(CHUNK1 * 32) / 256, 256, 0, s1>>>(x, CHUNK0, CHUNK1);
    k_bgemm<64><<<dim3(5, CHUNK1 / 128), 256, SMEM64, s1>>>(
        txh, txl, 128, w1h + 128 * 320, w1l + 128 * 320,
        nullptr, nullptr, 0, nullptr, nullptr,
        128, 0, 320, CHUNK0, NN, 300,
        nullptr, h1f, nullptr, nullptr, 1,
        nullptr, nullptr, hh, hl, 320);
    cudaEventRecord(evB1, s1);

    // ---- s0: layer 2 combined GEMM (WN=128): y2x = h @ [W2[1] | W2[0]] ----
    cudaStreamWaitEvent(0, evB1, 0);
    k_bgemm<128><<<dim3(2, MP / 128), 256, SMEM128>>>(
        hh, hl, 320, w2h, w2l,
        nullptr, nullptr, 0, nullptr, nullptr,
        320, 0, 256, 0, NN, 256,
        nullptr, nullptr, nullptr, nullptr, 0,
        y2x, nullptr, nullptr, nullptr, 256);
    k_gather<25, 64><<<(NN * 32 + 255) / 256, 256>>>(y2x, t2);
    cudaStreamWaitEvent(0, evS2, 0);
    k_post<<<(NN * 25 + 255) / 256, 256>>>(y2x, t2, b2, x2, z);
    cudaEventRecord(evZ, 0);

    // ---- s0: layer 3 output chain ----
    k_small2<<<(NN + 255) / 256, 256>>>(x2, W3 + 200, nullptr, nullptr, y3);
    k_gather2<<<(NN + 255) / 256, 256>>>(y3, t3);
    k_small2<<<(NN + 255) / 256, 256>>>(x2, W3, b3, t3, out);

    // ---- s1: loss chain, concurrent with layer 3 ----
    cudaStreamWaitEvent(s1, evZ, 0);
    k_loss<<<(2 * PP * 8 + 255) / 256, 256, 0, s1>>>(ep, en);
    k_final<<<1, 32, 0, s1>>>(c1, c2, out);
    cudaEventRecord(evSide, s1);

    // ---- join ----
    cudaStreamWaitEvent(0, evSide, 0);
}

// round 13
// speedup vs baseline: 1.1183x; 1.0334x over previous
#include <cuda_runtime.h>
#include <cuda_bf16.h>
#include <math.h>

#define NN 50000
#define MP 50048          // NN padded to 128
#define EE 800000
#define PP 400000
#define NB_SCAN 196       // ceil(NN/256)
#define CHUNK0 25088      // 196*128
#define CHUNK1 (MP - CHUNK0)

typedef unsigned short ushort_t;
typedef unsigned int uint_t;

// ---------------- scratch (device globals) ----------------------------------
static __device__ __align__(16) ushort_t g_xh[MP * 128];
static __device__ __align__(16) ushort_t g_xl[MP * 128];
static __device__ __align__(16) ushort_t g_txh[MP * 128];
static __device__ __align__(16) ushort_t g_txl[MP * 128];
static __device__ __align__(16) ushort_t g_hh[MP * 320];
static __device__ __align__(16) ushort_t g_hl[MP * 320];
static __device__ __align__(16) ushort_t g_w1h[2 * 128 * 320];
static __device__ __align__(16) ushort_t g_w1l[2 * 128 * 320];
static __device__ __align__(16) ushort_t g_w2h[320 * 256];   // cat: [W2[1] | W2[0]]
static __device__ __align__(16) ushort_t g_w2l[320 * 256];
static __device__ __align__(16) ushort_t g_l1h[128 * 128];
static __device__ __align__(16) ushort_t g_l1l[128 * 128];
static __device__ __align__(16) ushort_t g_l2h[128 * 128];
static __device__ __align__(16) ushort_t g_l2l[128 * 128];

static __device__ __align__(16) float g_h1f[NN * 300];       // x@W1[0]+b1 (fp32)
static __device__ __align__(16) float g_y2x[MP * 256];       // [y2 | x1raw]
static __device__ __align__(16) float g_x2[NN * 100];
static __device__ __align__(16) float g_z[NN * 100];
static __device__ __align__(16) float g_y3[NN * 2];
static __device__ float g_dinv[NN];
static __device__ int   g_deg[NN];
static __device__ int   g_cnt[NN];
static __device__ int   g_fill[NN];
static __device__ int   g_rowptr[NN + 1];
static __device__ int   g_bsum[NB_SCAN];
static __device__ int   g_boff[NB_SCAN];
static __device__ int   g_csr_src[EE];
static __device__ float g_csr_w[EE];
static __device__ float g_loss;

// ---------------- helpers ----------------------------------------------------
__device__ __forceinline__ void split1(float v, ushort_t& h, ushort_t& l) {
    __nv_bfloat16 bh = __float2bfloat16_rn(v);
    h = __bfloat16_as_ushort(bh);
    float r = v - __bfloat162float(bh);
    l = __bfloat16_as_ushort(__float2bfloat16_rn(r));
}

__device__ __forceinline__ void ldsm4(uint_t* r, uint_t addr) {
    asm volatile("ldmatrix.sync.aligned.m8n8.x4.shared.b16 {%0,%1,%2,%3}, [%4];"
                 : "=r"(r[0]), "=r"(r[1]), "=r"(r[2]), "=r"(r[3]) : "r"(addr));
}
__device__ __forceinline__ void ldsm4t(uint_t* r, uint_t addr) {
    asm volatile("ldmatrix.sync.aligned.m8n8.x4.trans.shared.b16 {%0,%1,%2,%3}, [%4];"
                 : "=r"(r[0]), "=r"(r[1]), "=r"(r[2]), "=r"(r[3]) : "r"(addr));
}
__device__ __forceinline__ void mma_bf16(float* d, const uint_t* a, uint_t b0, uint_t b1) {
    asm volatile(
        "mma.sync.aligned.m16n8k16.row.col.f32.bf16.bf16.f32 "
        "{%0,%1,%2,%3},{%4,%5,%6,%7},{%8,%9},{%0,%1,%2,%3};"
        : "+f"(d[0]), "+f"(d[1]), "+f"(d[2]), "+f"(d[3])
        : "r"(a[0]), "r"(a[1]), "r"(a[2]), "r"(a[3]), "r"(b0), "r"(b1));
}
__device__ __forceinline__ void cp16(uint_t dst, const void* src) {
    asm volatile("cp.async.cg.shared.global [%0], [%1], 16;\n" :: "r"(dst), "l"(src));
}

// ---------------- graph preprocessing ----------------------------------------
__global__ void k_zero() {
    int i = blockIdx.x * blockDim.x + threadIdx.x;
    if (i < NN) { g_deg[i] = 0; g_cnt[i] = 0; g_fill[i] = 0; }
    if (i == 0) g_loss = 0.0f;
}

__global__ void k_degcnt(const int* __restrict__ ei) {
    int e = blockIdx.x * blockDim.x + threadIdx.x;
    if (e < EE) {
        atomicAdd(&g_deg[ei[e]], 1);
        atomicAdd(&g_cnt[ei[EE + e]], 1);
    }
}

__global__ void k_dinv() {
    int i = blockIdx.x * blockDim.x + threadIdx.x;
    if (i < NN) {
        int d = g_deg[i];
        g_dinv[i] = (d > 0) ? rsqrtf((float)d) : 0.0f;
    }
}

__global__ void k_scan1() {
    __shared__ int s[256];
    int t = threadIdx.x;
    int i = blockIdx.x * 256 + t;
    s[t] = (i < NN) ? g_cnt[i] : 0;
    __syncthreads();
    for (int o = 128; o > 0; o >>= 1) {
        if (t < o) s[t] += s[t + o];
        __syncthreads();
    }
    if (t == 0) g_bsum[blockIdx.x] = s[0];
}

__global__ void k_scan2() {
    __shared__ int s[256];
    int t = threadIdx.x;
    int v = (t < NB_SCAN) ? g_bsum[t] : 0;
    s[t] = v;
    __syncthreads();
    for (int o = 1; o < 256; o <<= 1) {
        int tv = (t >= o) ? s[t - o] : 0;
        __syncthreads();
        s[t] += tv;
        __syncthreads();
    }
    if (t < NB_SCAN) g_boff[t] = s[t] - v;
    if (t == 255) g_rowptr[NN] = s[255];
}

__global__ void k_scan3() {
    __shared__ int s[256];
    int t = threadIdx.x;
    int i = blockIdx.x * 256 + t;
    int v = (i < NN) ? g_cnt[i] : 0;
    s[t] = v;
    __syncthreads();
    for (int o = 1; o < 256; o <<= 1) {
        int tv = (t >= o) ? s[t - o] : 0;
        __syncthreads();
        s[t] += tv;
        __syncthreads();
    }
    if (i < NN) g_rowptr[i] = g_boff[blockIdx.x] + s[t] - v;
}

__global__ void k_fill(const int* __restrict__ ei) {
    int e = blockIdx.x * blockDim.x + threadIdx.x;
    if (e < EE) {
        int s = ei[e];
        int d = ei[EE + e];
        int pos = g_rowptr[d] + atomicAdd(&g_fill[d], 1);
        g_csr_src[pos] = s;
        g_csr_w[pos] = -g_dinv[s] * g_dinv[d];
    }
}

// ---------------- conversions --------------------------------------------------
__global__ void k_conv_x(const float* __restrict__ x) {
    int idx = blockIdx.x * blockDim.x + threadIdx.x;
    if (idx >= MP * 32) return;
    int row = idx >> 5;
    float4 v = (row < NN) ? ((const float4*)x)[idx] : make_float4(0.f, 0.f, 0.f, 0.f);
    ushort_t h0, h1, h2, h3, l0, l1, l2, l3;
    split1(v.x, h0, l0); split1(v.y, h1, l1);
    split1(v.z, h2, l2); split1(v.w, h3, l3);
    ((uint2*)g_xh)[idx] = make_uint2((uint_t)h0 | ((uint_t)h1 << 16), (uint_t)h2 | ((uint_t)h3 << 16));
    ((uint2*)g_xl)[idx] = make_uint2((uint_t)l0 | ((uint_t)l1 << 16), (uint_t)l2 | ((uint_t)l3 << 16));
}

__global__ void k_conv_w(const float* __restrict__ src, ushort_t* __restrict__ dh,
                         ushort_t* __restrict__ dl, int K, int N, int Kp, int Np, int trans) {
    int idx = blockIdx.x * blockDim.x + threadIdx.x;
    if (idx >= Kp * Np) return;
    int k = idx / Np, n = idx % Np;
    float v = 0.f;
    if (k < K && n < N) v = trans ? src[n * K + k] : src[k * N + n];
    ushort_t h, l;
    split1(v, h, l);
    dh[idx] = h;
    dl[idx] = l;
}

// W2 concatenated conversion: src [300,100] -> dst[320,256] cols [coff, coff+128)
__global__ void k_conv_wc(const float* __restrict__ src, ushort_t* __restrict__ dh,
                          ushort_t* __restrict__ dl, int coff) {
    int idx = blockIdx.x * blockDim.x + threadIdx.x;
    if (idx >= 320 * 128) return;
    int k = idx >> 7, n = idx & 127;
    float v = (k < 300 && n < 100) ? src[k * 100 + n] : 0.f;
    ushort_t h, l;
    split1(v, h, l);
    dh[k * 256 + coff + n] = h;
    dl[k * 256 + coff + n] = l;
}

__global__ void k_zero_hpad() {
    int idx = blockIdx.x * blockDim.x + threadIdx.x;
    if (idx < (MP - NN) * 320) {
        g_hh[(size_t)NN * 320 + idx] = 0;
        g_hl[(size_t)NN * 320 + idx] = 0;
    }
}

// ---------------- gathers -------------------------------------------------------
// row-chunked gather of x into bf16 hi/lo split
__global__ void k_gather128bf(const float* __restrict__ x, int rowBeg, int nRows) {
    int g0 = (blockIdx.x * blockDim.x + threadIdx.x) >> 5;
    int lane = threadIdx.x & 31;
    if (g0 >= nRows) return;
    int gw = rowBeg + g0;
    float4 acc = make_float4(0.f, 0.f, 0.f, 0.f);
    if (gw < NN) {
        int beg = g_rowptr[gw], end = g_rowptr[gw + 1];
        const float4* sf = (const float4*)x;
        for (int e = beg; e < end; e++) {
            int s = g_csr_src[e];
            float w = g_csr_w[e];
            float4 v = sf[(size_t)s * 32 + lane];
            acc.x += w * v.x; acc.y += w * v.y;
            acc.z += w * v.z; acc.w += w * v.w;
        }
    }
    ushort_t h0, h1, h2, h3, l0, l1, l2, l3;
    split1(acc.x, h0, l0); split1(acc.y, h1, l1);
    split1(acc.z, h2, l2); split1(acc.w, h3, l3);
    size_t idx = (size_t)gw * 32 + lane;
    ((uint2*)g_txh)[idx] = make_uint2((uint_t)h0 | ((uint_t)h1 << 16), (uint_t)h2 | ((uint_t)h3 << 16));
    ((uint2*)g_txl)[idx] = make_uint2((uint_t)l0 | ((uint_t)l1 << 16), (uint_t)l2 | ((uint_t)l3 << 16));
}

// fused layer-2 gather + epilogue: warp per node, lanes 0-24 handle float4 groups.
// t2 = gather(y2) [y2 = y2x cols 0..99]; x1 = relu(x1raw + b2 + t2);
// x2 = x1 + r1 (in place), z = x1 + r2 (in place)
__global__ void k_gpost(const float* __restrict__ y2x, const float* __restrict__ b2,
                        float* __restrict__ x2, float* __restrict__ z) {
    int gw = (blockIdx.x * blockDim.x + threadIdx.x) >> 5;
    int lane = threadIdx.x & 31;
    if (gw >= NN || lane >= 25) return;
    int beg = g_rowptr[gw], end = g_rowptr[gw + 1];
    const float4* sf = (const float4*)y2x;
    float4 acc = make_float4(0.f, 0.f, 0.f, 0.f);
    for (int e = beg; e < end; e++) {
        int s = g_csr_src[e];
        float w = g_csr_w[e];
        float4 v = sf[(size_t)s * 64 + lane];
        acc.x += w * v.x; acc.y += w * v.y;
        acc.z += w * v.z; acc.w += w * v.w;
    }
    float4 raw = sf[(size_t)gw * 64 + 32 + lane];
    float4 bv = ((const float4*)b2)[lane];
    size_t idx = (size_t)gw * 25 + lane;
    float4 r1 = ((const float4*)x2)[idx];
    float4 r2 = ((const float4*)z)[idx];
    float v0 = fmaxf(raw.x + bv.x + acc.x, 0.f);
    float v1 = fmaxf(raw.y + bv.y + acc.y, 0.f);
    float v2 = fmaxf(raw.z + bv.z + acc.z, 0.f);
    float v3 = fmaxf(raw.w + bv.w + acc.w, 0.f);
    ((float4*)x2)[idx] = make_float4(v0 + r1.x, v1 + r1.y, v2 + r1.z, v3 + r1.w);
    ((float4*)z)[idx]  = make_float4(v0 + r2.x, v1 + r2.y, v2 + r2.z, v3 + r2.w);
}

// ---------------- bf16x3 tensor-core GEMM, 2-stage cp.async, WN-templated -------
#define A_L_OFF 5120

template <int WN>
__device__ __forceinline__ void issue_tile(
    uint_t sbase, int tid,
    const ushort_t* __restrict__ Ah, const ushort_t* __restrict__ Al, int lda, int rowBase,
    const ushort_t* __restrict__ Bh, const ushort_t* __restrict__ Bl, int ldb, int colBase,
    int k0) {
    constexpr int BST = WN + 8;
    constexpr int B_H_OFFt = 10240;
    constexpr int B_L_OFFt = 10240 + 32 * BST;
    constexpr int BCH = WN / 8;
#pragma unroll
    for (int i = 0; i < 4; i++) {
        int idx = tid + i * 256;
        int arr = idx >> 9, rem = idx & 511;
        int row = rem >> 2, ch = rem & 3;
        const ushort_t* src = (arr ? Al : Ah) + (size_t)(rowBase + row) * lda + k0 + ch * 8;
        uint_t dst = sbase + (uint_t)((arr ? A_L_OFF : 0) + row * 40 + ch * 8) * 2;
        cp16(dst, src);
    }
    constexpr int BTOT = 2 * 32 * BCH;
#pragma unroll
    for (int i = 0; i < BTOT / 256; i++) {
        int idx = tid + i * 256;
        int arr = (idx >= 32 * BCH) ? 1 : 0;
        int rem = idx - arr * 32 * BCH;
        int row = rem / BCH, ch = rem % BCH;
        const ushort_t* src = (arr ? Bl : Bh) + (size_t)(k0 + row) * ldb + colBase + ch * 8;
        uint_t dst = sbase + (uint_t)((arr ? B_L_OFFt : B_H_OFFt) + row * BST + ch * 8) * 2;
        cp16(dst, src);
    }
    asm volatile("cp.async.commit_group;\n");
}

template <int WN>
__global__ __launch_bounds__(256)
void k_bgemm(const ushort_t* __restrict__ Ah1, const ushort_t* __restrict__ Al1, int lda1,
             const ushort_t* __restrict__ Bh1, const ushort_t* __restrict__ Bl1,
             const ushort_t* __restrict__ Ah2, const ushort_t* __restrict__ Al2, int lda2,
             const ushort_t* __restrict__ Bh2, const ushort_t* __restrict__ Bl2,
             int K1, int K2, int ldb, int rowOff,
             int M, int N,
             const float* __restrict__ bias, const float* __restrict__ addend,
             const float* __restrict__ post1, const float* __restrict__ post2, int relu,
             float* __restrict__ Cf1, float* __restrict__ Cf2,
             ushort_t* __restrict__ Ch, ushort_t* __restrict__ Cl,
             int ldc) {
    constexpr int BST = WN + 8;
    constexpr int B_H_OFFt = 10240;
    constexpr int STAGE = 10240 + 64 * BST;
    constexpr int NP = WN / 32;
    constexpr int NREG = WN / 16;

    extern __shared__ __align__(16) ushort_t sm[];
    uint_t sbase0 = (uint_t)__cvta_generic_to_shared(sm);

    int tid = threadIdx.x, lane = tid & 31, wid = tid >> 5;
    int warp_m = wid & 3, warp_n = wid >> 2;
    int rowBase = rowOff + blockIdx.y * 128, colBase = blockIdx.x * WN;

    float acc[2][NREG][4];
#pragma unroll
    for (int m = 0; m < 2; m++)
#pragma unroll
        for (int n = 0; n < NREG; n++)
#pragma unroll
            for (int q = 0; q < 4; q++) acc[m][n][q] = 0.f;

    int T1 = K1 / 32;
    int T2 = (Ah2 != nullptr) ? (K2 / 32) : 0;
    int T = T1 + T2;

#define ISSUE(t)                                                                          \
    do {                                                                                  \
        int _t = (t);                                                                     \
        uint_t _sb = sbase0 + (uint_t)((_t & 1) * STAGE) * 2;                             \
        if (_t < T1)                                                                      \
            issue_tile<WN>(_sb, tid, Ah1, Al1, lda1, rowBase, Bh1, Bl1, ldb, colBase, _t * 32); \
        else                                                                              \
            issue_tile<WN>(_sb, tid, Ah2, Al2, lda2, rowBase, Bh2, Bl2, ldb, colBase, (_t - T1) * 32); \
    } while (0)

    ISSUE(0);

    for (int t = 0; t < T; t++) {
        if (t + 1 < T) {
            ISSUE(t + 1);
            asm volatile("cp.async.wait_group 1;\n");
        } else {
            asm volatile("cp.async.wait_group 0;\n");
        }
        __syncthreads();

        uint_t sA = sbase0 + (uint_t)((t & 1) * STAGE) * 2;
        uint_t sB = sA + (uint_t)B_H_OFFt * 2;

#pragma unroll
        for (int kk = 0; kk < 32; kk += 16) {
            uint_t ah[2][4], al[2][4], bh[NP][4], bl[NP][4];
            int g = lane >> 3, r = lane & 7;
#pragma unroll
            for (int m = 0; m < 2; m++) {
                int arow = warp_m * 32 + m * 16 + r + (g & 1) * 8;
                int acol = kk + (g >> 1) * 8;
                uint_t off = (uint_t)(arow * 40 + acol) * 2;
                ldsm4(ah[m], sA + off);
                ldsm4(al[m], sA + (uint_t)A_L_OFF * 2 + off);
            }
#pragma unroll
            for (int np = 0; np < NP; np++) {
                int brow = kk + r + (g & 1) * 8;
                int bcol = warp_n * (WN / 2) + np * 16 + (g >> 1) * 8;
                uint_t off = (uint_t)(brow * BST + bcol) * 2;
                ldsm4t(bh[np], sB + off);
                ldsm4t(bl[np], sB + (uint_t)(32 * BST) * 2 + off);
            }
#pragma unroll
            for (int m = 0; m < 2; m++)
#pragma unroll
                for (int n = 0; n < NREG; n++) {
                    uint_t b0h = bh[n >> 1][(n & 1) * 2], b1h = bh[n >> 1][(n & 1) * 2 + 1];
                    uint_t b0l = bl[n >> 1][(n & 1) * 2], b1l = bl[n >> 1][(n & 1) * 2 + 1];
                    mma_bf16(acc[m][n], ah[m], b0h, b1h);  // hi*hi
                    mma_bf16(acc[m][n], ah[m], b0l, b1l);  // hi*lo
                    mma_bf16(acc[m][n], al[m], b0h, b1h);  // lo*hi
                }
        }
        __syncthreads();
    }
#undef ISSUE

    // epilogue
#pragma unroll
    for (int m = 0; m < 2; m++)
#pragma unroll
        for (int n = 0; n < NREG; n++) {
#pragma unroll
            for (int half = 0; half < 2; half++) {
                float v0 = acc[m][n][half * 2 + 0];
                float v1 = acc[m][n][half * 2 + 1];
                int gr = rowBase + warp_m * 32 + m * 16 + (lane >> 2) + half * 8;
                int gc = colBase + warp_n * (WN / 2) + n * 8 + (lane & 3) * 2;
                if (gr >= M || gc >= N) continue;
                if (bias) { v0 += bias[gc]; v1 += bias[gc + 1]; }
                if (addend) {
                    v0 += addend[(size_t)gr * N + gc];
                    v1 += addend[(size_t)gr * N + gc + 1];
                }
                if (relu) { v0 = fmaxf(v0, 0.f); v1 = fmaxf(v1, 0.f); }
                size_t oidx = (size_t)gr * ldc + gc;
                if (Cf1) {
                    float a0 = v0, a1 = v1;
                    if (post1) {
                        float2 p = *(const float2*)&post1[oidx];
                        a0 += p.x; a1 += p.y;
                    }
                    float2 o; o.x = a0; o.y = a1;
                    *(float2*)&Cf1[oidx] = o;
                }
                if (Cf2) {
                    float a0 = v0, a1 = v1;
                    if (post2) {
                        float2 p = *(const float2*)&post2[oidx];
                        a0 += p.x; a1 += p.y;
                    }
                    float2 o; o.x = a0; o.y = a1;
                    *(float2*)&Cf2[oidx] = o;
                }
                if (Ch) {
                    ushort_t h0, l0, h1, l1;
                    split1(v0, h0, l0);
                    split1(v1, h1, l1);
                    *(uint_t*)&Ch[oidx] = (uint_t)h0 | ((uint_t)h1 << 16);
                    *(uint_t*)&Cl[oidx] = (uint_t)l0 | ((uint_t)l1 << 16);
                }
            }
        }
}

#define SMEM64  ((10240 + 64 * 72) * 4)
#define SMEM128 ((10240 + 64 * 136) * 4)

// ---------------- fused layer-3 dual small GEMM -----------------------------------
// out[n,:] = x2[n]@W3[0] + b3 ;  y3[n,:] = x2[n]@W3[1]   (one x2 pass)
__global__ void k_small2two(const float* __restrict__ X, const float* __restrict__ W3,
                            const float* __restrict__ b3,
                            float* __restrict__ y3, float* __restrict__ outp) {
    __shared__ float w[400];
    for (int i = threadIdx.x; i < 400; i += blockDim.x) w[i] = W3[i];
    __syncthreads();
    int n = blockIdx.x * blockDim.x + threadIdx.x;
    if (n >= NN) return;
    const float4* xr = (const float4*)X + (size_t)n * 25;
    float a0 = 0.f, a1 = 0.f, s0 = 0.f, s1 = 0.f;
#pragma unroll
    for (int k = 0; k < 25; k++) {
        float4 v = xr[k];
        int b = 4 * k;
        a0 += v.x * w[(b + 0) * 2] + v.y * w[(b + 1) * 2] +
              v.z * w[(b + 2) * 2] + v.w * w[(b + 3) * 2];
        a1 += v.x * w[(b + 0) * 2 + 1] + v.y * w[(b + 1) * 2 + 1] +
              v.z * w[(b + 2) * 2 + 1] + v.w * w[(b + 3) * 2 + 1];
        s0 += v.x * w[200 + (b + 0) * 2] + v.y * w[200 + (b + 1) * 2] +
              v.z * w[200 + (b + 2) * 2] + v.w * w[200 + (b + 3) * 2];
        s1 += v.x * w[200 + (b + 0) * 2 + 1] + v.y * w[200 + (b + 1) * 2 + 1] +
              v.z * w[200 + (b + 2) * 2 + 1] + v.w * w[200 + (b + 3) * 2 + 1];
    }
    outp[2 * n] = a0 + b3[0];
    outp[2 * n + 1] = a1 + b3[1];
    y3[2 * n] = s0;
    y3[2 * n + 1] = s1;
}

// gather y3 by CSR and accumulate into out
__global__ void k_g2add(const float* __restrict__ SF, float* __restrict__ out) {
    int n = blockIdx.x * blockDim.x + threadIdx.x;
    if (n >= NN) return;
    int beg = g_rowptr[n], end = g_rowptr[n + 1];
    float a0 = 0.f, a1 = 0.f;
    for (int e = beg; e < end; e++) {
        int s = g_csr_src[e];
        float w = g_csr_w[e];
        a0 += w * SF[2 * s];
        a1 += w * SF[2 * s + 1];
    }
    out[2 * n] += a0;
    out[2 * n + 1] += a1;
}

// ---------------- link-prediction loss: 8 threads per pair, coalesced ------------
__global__ void k_loss(const int* __restrict__ ep, const int* __restrict__ en) {
    int gid = blockIdx.x * blockDim.x + threadIdx.x;
    int pair = gid >> 3;
    int sub = gid & 7;
    float term = 0.f;
    if (pair < 2 * PP) {
        int a, b;
        bool pos = (pair < PP);
        if (pos) { a = ep[pair]; b = ep[PP + pair]; }
        else { int j = pair - PP; a = en[j]; b = en[PP + j]; }
        const float4* za = (const float4*)g_z + (size_t)a * 25;
        const float4* zb = (const float4*)g_z + (size_t)b * 25;
        float s = 0.f;
#pragma unroll
        for (int k = sub; k < 25; k += 8) {
            float4 u = za[k], v = zb[k];
            s += u.x * v.x + u.y * v.y + u.z * v.z + u.w * v.w;
        }
        s += __shfl_down_sync(0xffffffff, s, 4);
        s += __shfl_down_sync(0xffffffff, s, 2);
        s += __shfl_down_sync(0xffffffff, s, 1);
        if (sub == 0) {
            float sig = 1.0f / (1.0f + expf(-s));
            float arg = pos ? (sig + 1e-15f) : (1.0f - sig + 1e-15f);
            term = logf(arg);
        }
    }
    __shared__ float red[256];
    red[threadIdx.x] = term;
    __syncthreads();
    for (int o = 128; o > 0; o >>= 1) {
        if (threadIdx.x < o) red[threadIdx.x] += red[threadIdx.x + o];
        __syncthreads();
    }
    if (threadIdx.x == 0) atomicAdd(&g_loss, red[0]);
}

__global__ void k_final(const float* __restrict__ c1, const float* __restrict__ c2,
                        float* __restrict__ out) {
    if (threadIdx.x == 0) {
        out[2 * NN + 0] = -g_loss / (float)PP;
        out[2 * NN + 1] = c1[0];
        out[2 * NN + 2] = c2[0];
    }
}

// ---------------- launch -----------------------------------------------------------
extern "C" void kernel_launch(void* const* d_in, const int* in_sizes, int n_in,
                              void* d_out, int out_size) {
    const float* x   = (const float*)d_in[0];
    const int*   ei  = (const int*)d_in[1];
    const int*   ep  = (const int*)d_in[2];
    const int*   en  = (const int*)d_in[3];
    const float* W1  = (const float*)d_in[4];
    const float* b1  = (const float*)d_in[5];
    const float* W2  = (const float*)d_in[6];
    const float* b2  = (const float*)d_in[7];
    const float* W3  = (const float*)d_in[8];
    const float* b3  = (const float*)d_in[9];
    const float* l1W = (const float*)d_in[10];
    const float* l1b = (const float*)d_in[11];
    const float* l2W = (const float*)d_in[12];
    const float* l2b = (const float*)d_in[13];
    const float* c1  = (const float*)d_in[14];
    const float* c2  = (const float*)d_in[15];
    float* out = (float*)d_out;

    static bool s_init = false;
    static cudaStream_t s1, s2;
    static cudaEvent_t evRoot, evConvX, evA, evS2, evZ, evSide, evFill, evB1;
    if (!s_init) {
        cudaFuncSetAttribute(k_bgemm<64>, cudaFuncAttributeMaxDynamicSharedMemorySize, SMEM64);
        cudaFuncSetAttribute(k_bgemm<128>, cudaFuncAttributeMaxDynamicSharedMemorySize, SMEM128);
        cudaStreamCreateWithFlags(&s1, cudaStreamNonBlocking);
        cudaStreamCreateWithFlags(&s2, cudaStreamNonBlocking);
        cudaEventCreateWithFlags(&evRoot, cudaEventDisableTiming);
        cudaEventCreateWithFlags(&evConvX, cudaEventDisableTiming);
        cudaEventCreateWithFlags(&evA, cudaEventDisableTiming);
        cudaEventCreateWithFlags(&evS2, cudaEventDisableTiming);
        cudaEventCreateWithFlags(&evZ, cudaEventDisableTiming);
        cudaEventCreateWithFlags(&evSide, cudaEventDisableTiming);
        cudaEventCreateWithFlags(&evFill, cudaEventDisableTiming);
        cudaEventCreateWithFlags(&evB1, cudaEventDisableTiming);
        s_init = true;
    }

    ushort_t *xh, *xl, *txh, *txl, *hh, *hl;
    ushort_t *w1h, *w1l, *w2h, *w2l, *l1h, *l1l, *l2h, *l2l;
    float *h1f, *y2x, *x2, *z, *y3;
    cudaGetSymbolAddress((void**)&xh, g_xh);   cudaGetSymbolAddress((void**)&xl, g_xl);
    cudaGetSymbolAddress((void**)&txh, g_txh); cudaGetSymbolAddress((void**)&txl, g_txl);
    cudaGetSymbolAddress((void**)&hh, g_hh);   cudaGetSymbolAddress((void**)&hl, g_hl);
    cudaGetSymbolAddress((void**)&w1h, g_w1h); cudaGetSymbolAddress((void**)&w1l, g_w1l);
    cudaGetSymbolAddress((void**)&w2h, g_w2h); cudaGetSymbolAddress((void**)&w2l, g_w2l);
    cudaGetSymbolAddress((void**)&l1h, g_l1h); cudaGetSymbolAddress((void**)&l1l, g_l1l);
    cudaGetSymbolAddress((void**)&l2h, g_l2h); cudaGetSymbolAddress((void**)&l2l, g_l2l);
    cudaGetSymbolAddress((void**)&h1f, g_h1f); cudaGetSymbolAddress((void**)&y2x, g_y2x);
    cudaGetSymbolAddress((void**)&x2, g_x2);   cudaGetSymbolAddress((void**)&z, g_z);
    cudaGetSymbolAddress((void**)&y3, g_y3);

    // ---- fork side streams ----
    cudaEventRecord(evRoot, 0);
    cudaStreamWaitEvent(s1, evRoot, 0);
    cudaStreamWaitEvent(s2, evRoot, 0);

    // ---- s1: conv_x, conv W1/W2, layer-1 part A ----
    k_conv_x<<<(MP * 32 + 255) / 256, 256, 0, s1>>>(x);
    cudaEventRecord(evConvX, s1);
    k_conv_w<<<(128 * 320 + 255) / 256, 256, 0, s1>>>(W1, w1h, w1l, 128, 300, 128, 320, 0);
    k_conv_w<<<(128 * 320 + 255) / 256, 256, 0, s1>>>(W1 + 128 * 300, w1h + 128 * 320, w1l + 128 * 320, 128, 300, 128, 320, 0);
    k_conv_wc<<<(320 * 128 + 255) / 256, 256, 0, s1>>>(W2 + 300 * 100, w2h, w2l, 0);
    k_conv_wc<<<(320 * 128 + 255) / 256, 256, 0, s1>>>(W2, w2h, w2l, 128);
    k_bgemm<64><<<dim3(5, MP / 128), 256, SMEM64, s1>>>(
        xh, xl, 128, w1h, w1l,
        nullptr, nullptr, 0, nullptr, nullptr,
        128, 0, 320, 0, NN, 300,
        b1, nullptr, nullptr, nullptr, 0,
        h1f, nullptr, nullptr, nullptr, 300);
    cudaEventRecord(evA, s1);

    // ---- s2: conv lin, lin GEMMs ----
    k_conv_w<<<(128 * 128 + 255) / 256, 256, 0, s2>>>(l1W, l1h, l1l, 128, 100, 128, 128, 1);
    k_conv_w<<<(128 * 128 + 255) / 256, 256, 0, s2>>>(l2W, l2h, l2l, 128, 100, 128, 128, 1);
    cudaStreamWaitEvent(s2, evConvX, 0);
    k_bgemm<64><<<dim3(2, MP / 128), 256, SMEM64, s2>>>(
        xh, xl, 128, l1h, l1l,
        nullptr, nullptr, 0, nullptr, nullptr,
        128, 0, 128, 0, NN, 100,
        l1b, nullptr, nullptr, nullptr, 1,
        x2, nullptr, nullptr, nullptr, 100);
    k_bgemm<64><<<dim3(2, MP / 128), 256, SMEM64, s2>>>(
        xh, xl, 128, l2h, l2l,
        nullptr, nullptr, 0, nullptr, nullptr,
        128, 0, 128, 0, NN, 100,
        l2b, nullptr, nullptr, nullptr, 1,
        z, nullptr, nullptr, nullptr, 100);
    cudaEventRecord(evS2, s2);

    // ---- s0: graph preprocessing chain ----
    k_zero<<<(NN + 255) / 256, 256>>>();
    k_degcnt<<<(EE + 255) / 256, 256>>>(ei);
    k_dinv<<<(NN + 255) / 256, 256>>>();
    k_scan1<<<NB_SCAN, 256>>>();
    k_scan2<<<1, 256>>>();
    k_scan3<<<NB_SCAN, 256>>>();
    k_fill<<<(EE + 255) / 256, 256>>>(ei);
    cudaEventRecord(evFill, 0);
    k_zero_hpad<<<((MP - NN) * 320 + 255) / 256, 256>>>();

    // ---- chunked gather + part-B pipeline ----
    k_gather128bf<<<(CHUNK0 * 32) / 256, 256>>>(x, 0, CHUNK0);
    cudaStreamWaitEvent(0, evA, 0);
    k_bgemm<64><<<dim3(5, CHUNK0 / 128), 256, SMEM64>>>(
        txh, txl, 128, w1h + 128 * 320, w1l + 128 * 320,
        nullptr, nullptr, 0, nullptr, nullptr,
        128, 0, 320, 0, NN, 300,
        nullptr, h1f, nullptr, nullptr, 1,
        nullptr, nullptr, hh, hl, 320);
    cudaStreamWaitEvent(s1, evFill, 0);
    k_gather128bf<<<(CHUNK1 * 32) / 256, 256, 0, s1>>>(x, CHUNK0, CHUNK1);
    k_bgemm<64><<<dim3(5, CHUNK1 / 128), 256, SMEM64, s1>>>(
        txh, txl, 128, w1h + 128 * 320, w1l + 128 * 320,
        nullptr, nullptr, 0, nullptr, nullptr,
        128, 0, 320, CHUNK0, NN, 300,
        nullptr, h1f, nullptr, nullptr, 1,
        nullptr, nullptr, hh, hl, 320);
    cudaEventRecord(evB1, s1);

    // ---- s0: layer 2 combined GEMM (WN=128): y2x = h @ [W2[1] | W2[0]] ----
    cudaStreamWaitEvent(0, evB1, 0);
    k_bgemm<128><<<dim3(2, MP / 128), 256, SMEM128>>>(
        hh, hl, 320, w2h, w2l,
        nullptr, nullptr, 0, nullptr, nullptr,
        320, 0, 256, 0, NN, 256,
        nullptr, nullptr, nullptr, nullptr, 0,
        y2x, nullptr, nullptr, nullptr, 256);
    // fused gather + epilogue (needs lin GEMM results r1/r2)
    cudaStreamWaitEvent(0, evS2, 0);
    k_gpost<<<(NN * 32 + 255) / 256, 256>>>(y2x, b2, x2, z);
    cudaEventRecord(evZ, 0);

    // ---- s0: layer 3 output chain (fused dual small GEMM + gather-add) ----
    k_small2two<<<(NN + 255) / 256, 256>>>(x2, W3, b3, y3, out);
    k_g2add<<<(NN + 255) / 256, 256>>>(y3, out);

    // ---- s1: loss chain, concurrent with layer 3 ----
    cudaStreamWaitEvent(s1, evZ, 0);
    k_loss<<<(2 * PP * 8 + 255) / 256, 256, 0, s1>>>(ep, en);
    k_final<<<1, 32, 0, s1>>>(c1, c2, out);
    cudaEventRecord(evSide, s1);

    // ---- join ----
    cudaStreamWaitEvent(0, evSide, 0);
}

// round 14
// speedup vs baseline: 1.1195x; 1.0011x over previous
#include <cuda_runtime.h>
#include <cuda_bf16.h>
#include <math.h>

#define NN 50000
#define MP 50048          // NN padded to 128
#define EE 800000
#define PP 400000
#define NB_SCAN 196       // ceil(NN/256)
#define CHUNK0 25088      // 196*128
#define CHUNK1 (MP - CHUNK0)

typedef unsigned short ushort_t;
typedef unsigned int uint_t;

// ---------------- scratch (device globals) ----------------------------------
static __device__ __align__(16) ushort_t g_xh[MP * 128];
static __device__ __align__(16) ushort_t g_xl[MP * 128];
static __device__ __align__(16) ushort_t g_txh[MP * 128];
static __device__ __align__(16) ushort_t g_txl[MP * 128];
static __device__ __align__(16) ushort_t g_hh[MP * 320];
static __device__ __align__(16) ushort_t g_hl[MP * 320];
static __device__ __align__(16) ushort_t g_w1h[2 * 128 * 320];
static __device__ __align__(16) ushort_t g_w1l[2 * 128 * 320];
static __device__ __align__(16) ushort_t g_w2h[320 * 256];    // cat: [W2[1] | W2[0]]
static __device__ __align__(16) ushort_t g_w2l[320 * 256];
static __device__ __align__(16) ushort_t g_lch[128 * 256];    // cat: [l1W^T | l2W^T | 0pad]
static __device__ __align__(16) ushort_t g_lcl[128 * 256];

static __device__ __align__(16) float g_h1f[NN * 300];        // x@W1[0]+b1 (fp32)
static __device__ __align__(16) float g_y2x[MP * 256];        // [y2 | x1raw]
static __device__ __align__(16) float g_rz[NN * 200];         // [x@l1^T | x@l2^T] raw
static __device__ __align__(16) float g_x2[NN * 100];
static __device__ __align__(16) float g_z[NN * 100];
static __device__ __align__(16) float g_y3[NN * 2];
static __device__ float g_dinv[NN];
static __device__ int   g_deg[NN];
static __device__ int   g_cnt[NN];
static __device__ int   g_fill[NN];
static __device__ int   g_rowptr[NN + 1];
static __device__ int   g_bsum[NB_SCAN];
static __device__ int   g_boff[NB_SCAN];
static __device__ int   g_csr_src[EE];
static __device__ float g_csr_w[EE];
static __device__ float g_loss;

// ---------------- helpers ----------------------------------------------------
__device__ __forceinline__ void split1(float v, ushort_t& h, ushort_t& l) {
    __nv_bfloat16 bh = __float2bfloat16_rn(v);
    h = __bfloat16_as_ushort(bh);
    float r = v - __bfloat162float(bh);
    l = __bfloat16_as_ushort(__float2bfloat16_rn(r));
}

__device__ __forceinline__ void ldsm4(uint_t* r, uint_t addr) {
    asm volatile("ldmatrix.sync.aligned.m8n8.x4.shared.b16 {%0,%1,%2,%3}, [%4];"
                 : "=r"(r[0]), "=r"(r[1]), "=r"(r[2]), "=r"(r[3]) : "r"(addr));
}
__device__ __forceinline__ void ldsm4t(uint_t* r, uint_t addr) {
    asm volatile("ldmatrix.sync.aligned.m8n8.x4.trans.shared.b16 {%0,%1,%2,%3}, [%4];"
                 : "=r"(r[0]), "=r"(r[1]), "=r"(r[2]), "=r"(r[3]) : "r"(addr));
}
__device__ __forceinline__ void mma_bf16(float* d, const uint_t* a, uint_t b0, uint_t b1) {
    asm volatile(
        "mma.sync.aligned.m16n8k16.row.col.f32.bf16.bf16.f32 "
        "{%0,%1,%2,%3},{%4,%5,%6,%7},{%8,%9},{%0,%1,%2,%3};"
        : "+f"(d[0]), "+f"(d[1]), "+f"(d[2]), "+f"(d[3])
        : "r"(a[0]), "r"(a[1]), "r"(a[2]), "r"(a[3]), "r"(b0), "r"(b1));
}
__device__ __forceinline__ void cp16(uint_t dst, const void* src) {
    asm volatile("cp.async.cg.shared.global [%0], [%1], 16;\n" :: "r"(dst), "l"(src));
}

// ---------------- graph preprocessing ----------------------------------------
__global__ void k_zero() {
    int i = blockIdx.x * blockDim.x + threadIdx.x;
    if (i < NN) { g_deg[i] = 0; g_cnt[i] = 0; g_fill[i] = 0; }
    if (i == 0) g_loss = 0.0f;
}

__global__ void k_degcnt(const int* __restrict__ ei) {
    int e = blockIdx.x * blockDim.x + threadIdx.x;
    if (e < EE) {
        atomicAdd(&g_deg[ei[e]], 1);
        atomicAdd(&g_cnt[ei[EE + e]], 1);
    }
}

// fused: per-node dinv + block-sum of cnt
__global__ void k_scan1() {
    __shared__ int s[256];
    int t = threadIdx.x;
    int i = blockIdx.x * 256 + t;
    if (i < NN) {
        int d = g_deg[i];
        g_dinv[i] = (d > 0) ? rsqrtf((float)d) : 0.0f;
    }
    s[t] = (i < NN) ? g_cnt[i] : 0;
    __syncthreads();
    for (int o = 128; o > 0; o >>= 1) {
        if (t < o) s[t] += s[t + o];
        __syncthreads();
    }
    if (t == 0) g_bsum[blockIdx.x] = s[0];
}

__global__ void k_scan2() {
    __shared__ int s[256];
    int t = threadIdx.x;
    int v = (t < NB_SCAN) ? g_bsum[t] : 0;
    s[t] = v;
    __syncthreads();
    for (int o = 1; o < 256; o <<= 1) {
        int tv = (t >= o) ? s[t - o] : 0;
        __syncthreads();
        s[t] += tv;
        __syncthreads();
    }
    if (t < NB_SCAN) g_boff[t] = s[t] - v;
    if (t == 255) g_rowptr[NN] = s[255];
}

__global__ void k_scan3() {
    __shared__ int s[256];
    int t = threadIdx.x;
    int i = blockIdx.x * 256 + t;
    int v = (i < NN) ? g_cnt[i] : 0;
    s[t] = v;
    __syncthreads();
    for (int o = 1; o < 256; o <<= 1) {
        int tv = (t >= o) ? s[t - o] : 0;
        __syncthreads();
        s[t] += tv;
        __syncthreads();
    }
    if (i < NN) g_rowptr[i] = g_boff[blockIdx.x] + s[t] - v;
}

__global__ void k_fill(const int* __restrict__ ei) {
    int e = blockIdx.x * blockDim.x + threadIdx.x;
    if (e < EE) {
        int s = ei[e];
        int d = ei[EE + e];
        int pos = g_rowptr[d] + atomicAdd(&g_fill[d], 1);
        g_csr_src[pos] = s;
        g_csr_w[pos] = -g_dinv[s] * g_dinv[d];
    }
}

// ---------------- conversions --------------------------------------------------
__global__ void k_conv_x(const float* __restrict__ x) {
    int idx = blockIdx.x * blockDim.x + threadIdx.x;
    if (idx >= MP * 32) return;
    int row = idx >> 5;
    float4 v = (row < NN) ? ((const float4*)x)[idx] : make_float4(0.f, 0.f, 0.f, 0.f);
    ushort_t h0, h1, h2, h3, l0, l1, l2, l3;
    split1(v.x, h0, l0); split1(v.y, h1, l1);
    split1(v.z, h2, l2); split1(v.w, h3, l3);
    ((uint2*)g_xh)[idx] = make_uint2((uint_t)h0 | ((uint_t)h1 << 16), (uint_t)h2 | ((uint_t)h3 << 16));
    ((uint2*)g_xl)[idx] = make_uint2((uint_t)l0 | ((uint_t)l1 << 16), (uint_t)l2 | ((uint_t)l3 << 16));
}

__global__ void k_conv_w(const float* __restrict__ src, ushort_t* __restrict__ dh,
                         ushort_t* __restrict__ dl, int K, int N, int Kp, int Np, int trans) {
    int idx = blockIdx.x * blockDim.x + threadIdx.x;
    if (idx >= Kp * Np) return;
    int k = idx / Np, n = idx % Np;
    float v = 0.f;
    if (k < K && n < N) v = trans ? src[n * K + k] : src[k * N + n];
    ushort_t h, l;
    split1(v, h, l);
    dh[idx] = h;
    dl[idx] = l;
}

// W2 concatenated conversion: src [300,100] -> dst[320,256] cols [coff, coff+128)
__global__ void k_conv_wc(const float* __restrict__ src, ushort_t* __restrict__ dh,
                          ushort_t* __restrict__ dl, int coff) {
    int idx = blockIdx.x * blockDim.x + threadIdx.x;
    if (idx >= 320 * 128) return;
    int k = idx >> 7, n = idx & 127;
    float v = (k < 300 && n < 100) ? src[k * 100 + n] : 0.f;
    ushort_t h, l;
    split1(v, h, l);
    dh[k * 256 + coff + n] = h;
    dl[k * 256 + coff + n] = l;
}

// lin cat conversion: [128, 256] K-row layout; cols 0-99=l1W^T, 100-199=l2W^T, rest 0
__global__ void k_conv_lcat(const float* __restrict__ l1W, const float* __restrict__ l2W) {
    int idx = blockIdx.x * blockDim.x + threadIdx.x;
    if (idx >= 128 * 256) return;
    int k = idx >> 8, n = idx & 255;
    float v = 0.f;
    if (n < 100) v = l1W[n * 128 + k];
    else if (n < 200) v = l2W[(n - 100) * 128 + k];
    ushort_t h, l;
    split1(v, h, l);
    g_lch[idx] = h;
    g_lcl[idx] = l;
}

// ---------------- gathers -------------------------------------------------------
__global__ void k_gather128bf(const float* __restrict__ x, int rowBeg, int nRows) {
    int g0 = (blockIdx.x * blockDim.x + threadIdx.x) >> 5;
    int lane = threadIdx.x & 31;
    if (g0 >= nRows) return;
    int gw = rowBeg + g0;
    float4 acc = make_float4(0.f, 0.f, 0.f, 0.f);
    if (gw < NN) {
        int beg = g_rowptr[gw], end = g_rowptr[gw + 1];
        const float4* sf = (const float4*)x;
        for (int e = beg; e < end; e++) {
            int s = g_csr_src[e];
            float w = g_csr_w[e];
            float4 v = sf[(size_t)s * 32 + lane];
            acc.x += w * v.x; acc.y += w * v.y;
            acc.z += w * v.z; acc.w += w * v.w;
        }
    }
    ushort_t h0, h1, h2, h3, l0, l1, l2, l3;
    split1(acc.x, h0, l0); split1(acc.y, h1, l1);
    split1(acc.z, h2, l2); split1(acc.w, h3, l3);
    size_t idx = (size_t)gw * 32 + lane;
    ((uint2*)g_txh)[idx] = make_uint2((uint_t)h0 | ((uint_t)h1 << 16), (uint_t)h2 | ((uint_t)h3 << 16));
    ((uint2*)g_txl)[idx] = make_uint2((uint_t)l0 | ((uint_t)l1 << 16), (uint_t)l2 | ((uint_t)l3 << 16));
}

// fused layer-2 gather + epilogue: warp per node, lanes 0-24 handle float4 groups.
// t2 = gather(y2); x1 = relu(x1raw + b2 + t2);
// r1 = relu(rz[:,0:100] + l1b); r2 = relu(rz[:,100:200] + l2b);
// x2 = x1 + r1; z = x1 + r2
__global__ void k_gpost(const float* __restrict__ y2x, const float* __restrict__ b2,
                        const float* __restrict__ rz,
                        const float* __restrict__ l1b, const float* __restrict__ l2b,
                        float* __restrict__ x2, float* __restrict__ z) {
    int gw = (blockIdx.x * blockDim.x + threadIdx.x) >> 5;
    int lane = threadIdx.x & 31;
    if (gw >= NN || lane >= 25) return;
    int beg = g_rowptr[gw], end = g_rowptr[gw + 1];
    const float4* sf = (const float4*)y2x;
    float4 acc = make_float4(0.f, 0.f, 0.f, 0.f);
    for (int e = beg; e < end; e++) {
        int s = g_csr_src[e];
        float w = g_csr_w[e];
        float4 v = sf[(size_t)s * 64 + lane];
        acc.x += w * v.x; acc.y += w * v.y;
        acc.z += w * v.z; acc.w += w * v.w;
    }
    float4 raw = sf[(size_t)gw * 64 + 32 + lane];
    float4 bv = ((const float4*)b2)[lane];
    float4 q1 = ((const float4*)(rz + (size_t)gw * 200))[lane];
    float4 q2 = ((const float4*)(rz + (size_t)gw * 200 + 100))[lane];
    float4 b1v = ((const float4*)l1b)[lane];
    float4 b2v = ((const float4*)l2b)[lane];
    float v0 = fmaxf(raw.x + bv.x + acc.x, 0.f);
    float v1 = fmaxf(raw.y + bv.y + acc.y, 0.f);
    float v2 = fmaxf(raw.z + bv.z + acc.z, 0.f);
    float v3 = fmaxf(raw.w + bv.w + acc.w, 0.f);
    float4 r1 = make_float4(fmaxf(q1.x + b1v.x, 0.f), fmaxf(q1.y + b1v.y, 0.f),
                            fmaxf(q1.z + b1v.z, 0.f), fmaxf(q1.w + b1v.w, 0.f));
    float4 r2 = make_float4(fmaxf(q2.x + b2v.x, 0.f), fmaxf(q2.y + b2v.y, 0.f),
                            fmaxf(q2.z + b2v.z, 0.f), fmaxf(q2.w + b2v.w, 0.f));
    size_t idx = (size_t)gw * 25 + lane;
    ((float4*)x2)[idx] = make_float4(v0 + r1.x, v1 + r1.y, v2 + r1.z, v3 + r1.w);
    ((float4*)z)[idx]  = make_float4(v0 + r2.x, v1 + r2.y, v2 + r2.z, v3 + r2.w);
}

// ---------------- bf16x3 tensor-core GEMM, 2-stage cp.async, WN-templated -------
#define A_L_OFF 5120

template <int WN>
__device__ __forceinline__ void issue_tile(
    uint_t sbase, int tid,
    const ushort_t* __restrict__ Ah, const ushort_t* __restrict__ Al, int lda, int rowBase,
    const ushort_t* __restrict__ Bh, const ushort_t* __restrict__ Bl, int ldb, int colBase,
    int k0) {
    constexpr int BST = WN + 8;
    constexpr int B_H_OFFt = 10240;
    constexpr int B_L_OFFt = 10240 + 32 * BST;
    constexpr int BCH = WN / 8;
#pragma unroll
    for (int i = 0; i < 4; i++) {
        int idx = tid + i * 256;
        int arr = idx >> 9, rem = idx & 511;
        int row = rem >> 2, ch = rem & 3;
        const ushort_t* src = (arr ? Al : Ah) + (size_t)(rowBase + row) * lda + k0 + ch * 8;
        uint_t dst = sbase + (uint_t)((arr ? A_L_OFF : 0) + row * 40 + ch * 8) * 2;
        cp16(dst, src);
    }
    constexpr int BTOT = 2 * 32 * BCH;
#pragma unroll
    for (int i = 0; i < BTOT / 256; i++) {
        int idx = tid + i * 256;
        int arr = (idx >= 32 * BCH) ? 1 : 0;
        int rem = idx - arr * 32 * BCH;
        int row = rem / BCH, ch = rem % BCH;
        const ushort_t* src = (arr ? Bl : Bh) + (size_t)(k0 + row) * ldb + colBase + ch * 8;
        uint_t dst = sbase + (uint_t)((arr ? B_L_OFFt : B_H_OFFt) + row * BST + ch * 8) * 2;
        cp16(dst, src);
    }
    asm volatile("cp.async.commit_group;\n");
}

template <int WN>
__global__ __launch_bounds__(256)
void k_bgemm(const ushort_t* __restrict__ Ah1, const ushort_t* __restrict__ Al1, int lda1,
             const ushort_t* __restrict__ Bh1, const ushort_t* __restrict__ Bl1,
             const ushort_t* __restrict__ Ah2, const ushort_t* __restrict__ Al2, int lda2,
             const ushort_t* __restrict__ Bh2, const ushort_t* __restrict__ Bl2,
             int K1, int K2, int ldb, int rowOff,
             int M, int N,
             const float* __restrict__ bias, const float* __restrict__ addend,
             const float* __restrict__ post1, const float* __restrict__ post2, int relu,
             float* __restrict__ Cf1, float* __restrict__ Cf2,
             ushort_t* __restrict__ Ch, ushort_t* __restrict__ Cl,
             int ldc) {
    constexpr int BST = WN + 8;
    constexpr int B_H_OFFt = 10240;
    constexpr int STAGE = 10240 + 64 * BST;
    constexpr int NP = WN / 32;
    constexpr int NREG = WN / 16;

    extern __shared__ __align__(16) ushort_t sm[];
    uint_t sbase0 = (uint_t)__cvta_generic_to_shared(sm);

    int tid = threadIdx.x, lane = tid & 31, wid = tid >> 5;
    int warp_m = wid & 3, warp_n = wid >> 2;
    int rowBase = rowOff + blockIdx.y * 128, colBase = blockIdx.x * WN;

    float acc[2][NREG][4];
#pragma unroll
    for (int m = 0; m < 2; m++)
#pragma unroll
        for (int n = 0; n < NREG; n++)
#pragma unroll
            for (int q = 0; q < 4; q++) acc[m][n][q] = 0.f;

    int T1 = K1 / 32;
    int T2 = (Ah2 != nullptr) ? (K2 / 32) : 0;
    int T = T1 + T2;

#define ISSUE(t)                                                                          \
    do {                                                                                  \
        int _t = (t);                                                                     \
        uint_t _sb = sbase0 + (uint_t)((_t & 1) * STAGE) * 2;                             \
        if (_t < T1)                                                                      \
            issue_tile<WN>(_sb, tid, Ah1, Al1, lda1, rowBase, Bh1, Bl1, ldb, colBase, _t * 32); \
        else                                                                              \
            issue_tile<WN>(_sb, tid, Ah2, Al2, lda2, rowBase, Bh2, Bl2, ldb, colBase, (_t - T1) * 32); \
    } while (0)

    ISSUE(0);

    for (int t = 0; t < T; t++) {
        if (t + 1 < T) {
            ISSUE(t + 1);
            asm volatile("cp.async.wait_group 1;\n");
        } else {
            asm volatile("cp.async.wait_group 0;\n");
        }
        __syncthreads();

        uint_t sA = sbase0 + (uint_t)((t & 1) * STAGE) * 2;
        uint_t sB = sA + (uint_t)B_H_OFFt * 2;

#pragma unroll
        for (int kk = 0; kk < 32; kk += 16) {
            uint_t ah[2][4], al[2][4], bh[NP][4], bl[NP][4];
            int g = lane >> 3, r = lane & 7;
#pragma unroll
            for (int m = 0; m < 2; m++) {
                int arow = warp_m * 32 + m * 16 + r + (g & 1) * 8;
                int acol = kk + (g >> 1) * 8;
                uint_t off = (uint_t)(arow * 40 + acol) * 2;
                ldsm4(ah[m], sA + off);
                ldsm4(al[m], sA + (uint_t)A_L_OFF * 2 + off);
            }
#pragma unroll
            for (int np = 0; np < NP; np++) {
                int brow = kk + r + (g & 1) * 8;
                int bcol = warp_n * (WN / 2) + np * 16 + (g >> 1) * 8;
                uint_t off = (uint_t)(brow * BST + bcol) * 2;
                ldsm4t(bh[np], sB + off);
                ldsm4t(bl[np], sB + (uint_t)(32 * BST) * 2 + off);
            }
#pragma unroll
            for (int m = 0; m < 2; m++)
#pragma unroll
                for (int n = 0; n < NREG; n++) {
                    uint_t b0h = bh[n >> 1][(n & 1) * 2], b1h = bh[n >> 1][(n & 1) * 2 + 1];
                    uint_t b0l = bl[n >> 1][(n & 1) * 2], b1l = bl[n >> 1][(n & 1) * 2 + 1];
                    mma_bf16(acc[m][n], ah[m], b0h, b1h);  // hi*hi
                    mma_bf16(acc[m][n], ah[m], b0l, b1l);  // hi*lo
                    mma_bf16(acc[m][n], al[m], b0h, b1h);  // lo*hi
                }
        }
        __syncthreads();
    }
#undef ISSUE

    // epilogue
#pragma unroll
    for (int m = 0; m < 2; m++)
#pragma unroll
        for (int n = 0; n < NREG; n++) {
#pragma unroll
            for (int half = 0; half < 2; half++) {
                float v0 = acc[m][n][half * 2 + 0];
                float v1 = acc[m][n][half * 2 + 1];
                int gr = rowBase + warp_m * 32 + m * 16 + (lane >> 2) + half * 8;
                int gc = colBase + warp_n * (WN / 2) + n * 8 + (lane & 3) * 2;
                if (gr >= M || gc >= N) continue;
                if (bias) { v0 += bias[gc]; v1 += bias[gc + 1]; }
                if (addend) {
                    v0 += addend[(size_t)gr * N + gc];
                    v1 += addend[(size_t)gr * N + gc + 1];
                }
                if (relu) { v0 = fmaxf(v0, 0.f); v1 = fmaxf(v1, 0.f); }
                size_t oidx = (size_t)gr * ldc + gc;
                if (Cf1) {
                    float a0 = v0, a1 = v1;
                    if (post1) {
                        float2 p = *(const float2*)&post1[oidx];
                        a0 += p.x; a1 += p.y;
                    }
                    float2 o; o.x = a0; o.y = a1;
                    *(float2*)&Cf1[oidx] = o;
                }
                if (Cf2) {
                    float a0 = v0, a1 = v1;
                    if (post2) {
                        float2 p = *(const float2*)&post2[oidx];
                        a0 += p.x; a1 += p.y;
                    }
                    float2 o; o.x = a0; o.y = a1;
                    *(float2*)&Cf2[oidx] = o;
                }
                if (Ch) {
                    ushort_t h0, l0, h1, l1;
                    split1(v0, h0, l0);
                    split1(v1, h1, l1);
                    *(uint_t*)&Ch[oidx] = (uint_t)h0 | ((uint_t)h1 << 16);
                    *(uint_t*)&Cl[oidx] = (uint_t)l0 | ((uint_t)l1 << 16);
                }
            }
        }
}

#define SMEM64  ((10240 + 64 * 72) * 4)
#define SMEM128 ((10240 + 64 * 136) * 4)

// ---------------- fused layer-3 dual small GEMM -----------------------------------
__global__ void k_small2two(const float* __restrict__ X, const float* __restrict__ W3,
                            const float* __restrict__ b3,
                            float* __restrict__ y3, float* __restrict__ outp) {
    __shared__ float w[400];
    for (int i = threadIdx.x; i < 400; i += blockDim.x) w[i] = W3[i];
    __syncthreads();
    int n = blockIdx.x * blockDim.x + threadIdx.x;
    if (n >= NN) return;
    const float4* xr = (const float4*)X + (size_t)n * 25;
    float a0 = 0.f, a1 = 0.f, s0 = 0.f, s1 = 0.f;
#pragma unroll
    for (int k = 0; k < 25; k++) {
        float4 v = xr[k];
        int b = 4 * k;
        a0 += v.x * w[(b + 0) * 2] + v.y * w[(b + 1) * 2] +
              v.z * w[(b + 2) * 2] + v.w * w[(b + 3) * 2];
        a1 += v.x * w[(b + 0) * 2 + 1] + v.y * w[(b + 1) * 2 + 1] +
              v.z * w[(b + 2) * 2 + 1] + v.w * w[(b + 3) * 2 + 1];
        s0 += v.x * w[200 + (b + 0) * 2] + v.y * w[200 + (b + 1) * 2] +
              v.z * w[200 + (b + 2) * 2] + v.w * w[200 + (b + 3) * 2];
        s1 += v.x * w[200 + (b + 0) * 2 + 1] + v.y * w[200 + (b + 1) * 2 + 1] +
              v.z * w[200 + (b + 2) * 2 + 1] + v.w * w[200 + (b + 3) * 2 + 1];
    }
    outp[2 * n] = a0 + b3[0];
    outp[2 * n + 1] = a1 + b3[1];
    y3[2 * n] = s0;
    y3[2 * n + 1] = s1;
}

__global__ void k_g2add(const float* __restrict__ SF, float* __restrict__ out) {
    int n = blockIdx.x * blockDim.x + threadIdx.x;
    if (n >= NN) return;
    int beg = g_rowptr[n], end = g_rowptr[n + 1];
    float a0 = 0.f, a1 = 0.f;
    for (int e = beg; e < end; e++) {
        int s = g_csr_src[e];
        float w = g_csr_w[e];
        a0 += w * SF[2 * s];
        a1 += w * SF[2 * s + 1];
    }
    out[2 * n] += a0;
    out[2 * n + 1] += a1;
}

// ---------------- link-prediction loss: 8 threads per pair, coalesced ------------
__global__ void k_loss(const int* __restrict__ ep, const int* __restrict__ en) {
    int gid = blockIdx.x * blockDim.x + threadIdx.x;
    int pair = gid >> 3;
    int sub = gid & 7;
    float term = 0.f;
    if (pair < 2 * PP) {
        int a, b;
        bool pos = (pair < PP);
        if (pos) { a = ep[pair]; b = ep[PP + pair]; }
        else { int j = pair - PP; a = en[j]; b = en[PP + j]; }
        const float4* za = (const float4*)g_z + (size_t)a * 25;
        const float4* zb = (const float4*)g_z + (size_t)b * 25;
        float s = 0.f;
#pragma unroll
        for (int k = sub; k < 25; k += 8) {
            float4 u = za[k], v = zb[k];
            s += u.x * v.x + u.y * v.y + u.z * v.z + u.w * v.w;
        }
        s += __shfl_down_sync(0xffffffff, s, 4);
        s += __shfl_down_sync(0xffffffff, s, 2);
        s += __shfl_down_sync(0xffffffff, s, 1);
        if (sub == 0) {
            float sig = 1.0f / (1.0f + expf(-s));
            float arg = pos ? (sig + 1e-15f) : (1.0f - sig + 1e-15f);
            term = logf(arg);
        }
    }
    __shared__ float red[256];
    red[threadIdx.x] = term;
    __syncthreads();
    for (int o = 128; o > 0; o >>= 1) {
        if (threadIdx.x < o) red[threadIdx.x] += red[threadIdx.x + o];
        __syncthreads();
    }
    if (threadIdx.x == 0) atomicAdd(&g_loss, red[0]);
}

__global__ void k_final(const float* __restrict__ c1, const float* __restrict__ c2,
                        float* __restrict__ out) {
    if (threadIdx.x == 0) {
        out[2 * NN + 0] = -g_loss / (float)PP;
        out[2 * NN + 1] = c1[0];
        out[2 * NN + 2] = c2[0];
    }
}

// ---------------- launch -----------------------------------------------------------
extern "C" void kernel_launch(void* const* d_in, const int* in_sizes, int n_in,
                              void* d_out, int out_size) {
    const float* x   = (const float*)d_in[0];
    const int*   ei  = (const int*)d_in[1];
    const int*   ep  = (const int*)d_in[2];
    const int*   en  = (const int*)d_in[3];
    const float* W1  = (const float*)d_in[4];
    const float* b1  = (const float*)d_in[5];
    const float* W2  = (const float*)d_in[6];
    const float* b2  = (const float*)d_in[7];
    const float* W3  = (const float*)d_in[8];
    const float* b3  = (const float*)d_in[9];
    const float* l1W = (const float*)d_in[10];
    const float* l1b = (const float*)d_in[11];
    const float* l2W = (const float*)d_in[12];
    const float* l2b = (const float*)d_in[13];
    const float* c1  = (const float*)d_in[14];
    const float* c2  = (const float*)d_in[15];
    float* out = (float*)d_out;

    static bool s_init = false;
    static cudaStream_t s1, s2;
    static cudaEvent_t evRoot, evConvX, evA, evS2, evZ, evSide, evFill, evB1;
    if (!s_init) {
        cudaFuncSetAttribute(k_bgemm<64>, cudaFuncAttributeMaxDynamicSharedMemorySize, SMEM64);
        cudaFuncSetAttribute(k_bgemm<128>, cudaFuncAttributeMaxDynamicSharedMemorySize, SMEM128);
        cudaStreamCreateWithFlags(&s1, cudaStreamNonBlocking);
        cudaStreamCreateWithFlags(&s2, cudaStreamNonBlocking);
        cudaEventCreateWithFlags(&evRoot, cudaEventDisableTiming);
        cudaEventCreateWithFlags(&evConvX, cudaEventDisableTiming);
        cudaEventCreateWithFlags(&evA, cudaEventDisableTiming);
        cudaEventCreateWithFlags(&evS2, cudaEventDisableTiming);
        cudaEventCreateWithFlags(&evZ, cudaEventDisableTiming);
        cudaEventCreateWithFlags(&evSide, cudaEventDisableTiming);
        cudaEventCreateWithFlags(&evFill, cudaEventDisableTiming);
        cudaEventCreateWithFlags(&evB1, cudaEventDisableTiming);
        s_init = true;
    }

    ushort_t *xh, *xl, *txh, *txl, *hh, *hl;
    ushort_t *w1h, *w1l, *w2h, *w2l;
    float *h1f, *y2x, *rz, *x2, *z, *y3;
    cudaGetSymbolAddress((void**)&xh, g_xh);   cudaGetSymbolAddress((void**)&xl, g_xl);
    cudaGetSymbolAddress((void**)&txh, g_txh); cudaGetSymbolAddress((void**)&txl, g_txl);
    cudaGetSymbolAddress((void**)&hh, g_hh);   cudaGetSymbolAddress((void**)&hl, g_hl);
    cudaGetSymbolAddress((void**)&w1h, g_w1h); cudaGetSymbolAddress((void**)&w1l, g_w1l);
    cudaGetSymbolAddress((void**)&w2h, g_w2h); cudaGetSymbolAddress((void**)&w2l, g_w2l);
    cudaGetSymbolAddress((void**)&h1f, g_h1f); cudaGetSymbolAddress((void**)&y2x, g_y2x);
    cudaGetSymbolAddress((void**)&rz, g_rz);
    cudaGetSymbolAddress((void**)&x2, g_x2);   cudaGetSymbolAddress((void**)&z, g_z);
    cudaGetSymbolAddress((void**)&y3, g_y3);

    ushort_t *lch, *lcl;
    cudaGetSymbolAddress((void**)&lch, g_lch);
    cudaGetSymbolAddress((void**)&lcl, g_lcl);

    // ---- fork side streams ----
    cudaEventRecord(evRoot, 0);
    cudaStreamWaitEvent(s1, evRoot, 0);
    cudaStreamWaitEvent(s2, evRoot, 0);

    // ---- s1: conv_x, conv W1/W2, layer-1 part A ----
    k_conv_x<<<(MP * 32 + 255) / 256, 256, 0, s1>>>(x);
    cudaEventRecord(evConvX, s1);
    k_conv_w<<<(128 * 320 + 255) / 256, 256, 0, s1>>>(W1, w1h, w1l, 128, 300, 128, 320, 0);
    k_conv_w<<<(128 * 320 + 255) / 256, 256, 0, s1>>>(W1 + 128 * 300, w1h + 128 * 320, w1l + 128 * 320, 128, 300, 128, 320, 0);
    k_conv_wc<<<(320 * 128 + 255) / 256, 256, 0, s1>>>(W2 + 300 * 100, w2h, w2l, 0);
    k_conv_wc<<<(320 * 128 + 255) / 256, 256, 0, s1>>>(W2, w2h, w2l, 128);
    k_bgemm<64><<<dim3(5, MP / 128), 256, SMEM64, s1>>>(
        xh, xl, 128, w1h, w1l,
        nullptr, nullptr, 0, nullptr, nullptr,
        128, 0, 320, 0, NN, 300,
        b1, nullptr, nullptr, nullptr, 0,
        h1f, nullptr, nullptr, nullptr, 300);
    cudaEventRecord(evA, s1);

    // ---- s2: lin cat conversion + single fused lin GEMM (raw, no bias/relu) ----
    k_conv_lcat<<<(128 * 256 + 255) / 256, 256, 0, s2>>>(l1W, l2W);
    cudaStreamWaitEvent(s2, evConvX, 0);
    k_bgemm<64><<<dim3(4, MP / 128), 256, SMEM64, s2>>>(
        xh, xl, 128, lch, lcl,
        nullptr, nullptr, 0, nullptr, nullptr,
        128, 0, 256, 0, NN, 200,
        nullptr, nullptr, nullptr, nullptr, 0,
        rz, nullptr, nullptr, nullptr, 200);
    cudaEventRecord(evS2, s2);

    // ---- s0: graph preprocessing chain ----
    k_zero<<<(NN + 255) / 256, 256>>>();
    k_degcnt<<<(EE + 255) / 256, 256>>>(ei);
    k_scan1<<<NB_SCAN, 256>>>();
    k_scan2<<<1, 256>>>();
    k_scan3<<<NB_SCAN, 256>>>();
    k_fill<<<(EE + 255) / 256, 256>>>(ei);
    cudaEventRecord(evFill, 0);

    // ---- chunked gather + part-B pipeline ----
    k_gather128bf<<<(CHUNK0 * 32) / 256, 256>>>(x, 0, CHUNK0);
    cudaStreamWaitEvent(0, evA, 0);
    k_bgemm<64><<<dim3(5, CHUNK0 / 128), 256, SMEM64>>>(
        txh, txl, 128, w1h + 128 * 320, w1l + 128 * 320,
        nullptr, nullptr, 0, nullptr, nullptr,
        128, 0, 320, 0, NN, 300,
        nullptr, h1f, nullptr, nullptr, 1,
        nullptr, nullptr, hh, hl, 320);
    cudaStreamWaitEvent(s1, evFill, 0);
    k_gather128bf<<<(CHUNK1 * 32) / 256, 256, 0, s1>>>(x, CHUNK0, CHUNK1);
    k_bgemm<64><<<dim3(5, CHUNK1 / 128), 256, SMEM64, s1>>>(
        txh, txl, 128, w1h + 128 * 320, w1l + 128 * 320,
        nullptr, nullptr, 0, nullptr, nullptr,
        128, 0, 320, CHUNK0, NN, 300,
        nullptr, h1f, nullptr, nullptr, 1,
        nullptr, nullptr, hh, hl, 320);
    cudaEventRecord(evB1, s1);

    // ---- s0: layer 2 combined GEMM (WN=128): y2x = h @ [W2[1] | W2[0]] ----
    cudaStreamWaitEvent(0, evB1, 0);
    k_bgemm<128><<<dim3(2, MP / 128), 256, SMEM128>>>(
        hh, hl, 320, w2h, w2l,
        nullptr, nullptr, 0, nullptr, nullptr,
        320, 0, 256, 0, NN, 256,
        nullptr, nullptr, nullptr, nullptr, 0,
        y2x, nullptr, nullptr, nullptr, 256);
    // fused gather + epilogue (needs raw lin results rz)
    cudaStreamWaitEvent(0, evS2, 0);
    k_gpost<<<(NN * 32 + 255) / 256, 256>>>(y2x, b2, rz, l1b, l2b, x2, z);
    cudaEventRecord(evZ, 0);

    // ---- s0: layer 3 output chain ----
    k_small2two<<<(NN + 255) / 256, 256>>>(x2, W3, b3, y3, out);
    k_g2add<<<(NN + 255) / 256, 256>>>(y3, out);

    // ---- s1: loss chain, concurrent with layer 3 ----
    cudaStreamWaitEvent(s1, evZ, 0);
    k_loss<<<(2 * PP * 8 + 255) / 256, 256, 0, s1>>>(ep, en);
    k_final<<<1, 32, 0, s1>>>(c1, c2, out);
    cudaEventRecord(evSide, s1);

    // ---- join ----
    cudaStreamWaitEvent(0, evSide, 0);
}